// round 10
// baseline (speedup 1.0000x reference)
#include <cuda_runtime.h>
#include <cuda_bf16.h>
#include <cuda_fp16.h>
#include <cstdint>

#define SQ 4096
#define DM 1024
#define NH 16
#define HS 64
#define QSCALE 0.125f
#define LOG2E 1.4426950408889634f
#define NEG -1e9f

// -------- scratch (no allocations allowed) --------
__device__ __align__(16) __nv_bfloat16 g_xhi[SQ * DM];
__device__ __align__(16) __nv_bfloat16 g_xlo[SQ * DM];
__device__ __align__(16) __nv_bfloat16 g_whi[4 * DM * DM];
__device__ __align__(16) __nv_bfloat16 g_wlo[4 * DM * DM];
__device__ __align__(16) __nv_bfloat16 g_qhi[NH * SQ * HS];
__device__ __align__(16) __nv_bfloat16 g_qlo[NH * SQ * HS];
__device__ __align__(16) __nv_bfloat16 g_khi[NH * SQ * HS];
__device__ __align__(16) __nv_bfloat16 g_klo[NH * SQ * HS];
__device__ __align__(16) __half       g_vhi[NH * SQ * HS];

// ============================================================================
// helpers
// ============================================================================
__device__ __forceinline__ uint32_t smem_u32(const void* p) {
    uint32_t a;
    asm("{ .reg .u64 t; cvta.to.shared.u64 t, %1; cvt.u32.u64 %0, t; }" : "=r"(a) : "l"(p));
    return a;
}

#define LDSM_X4(r0, r1, r2, r3, addr) \
    asm volatile("ldmatrix.sync.aligned.m8n8.x4.shared.b16 {%0,%1,%2,%3}, [%4];" \
                 : "=r"(r0), "=r"(r1), "=r"(r2), "=r"(r3) : "r"(addr))

#define LDSM_X4_T(r0, r1, r2, r3, addr) \
    asm volatile("ldmatrix.sync.aligned.m8n8.x4.trans.shared.b16 {%0,%1,%2,%3}, [%4];" \
                 : "=r"(r0), "=r"(r1), "=r"(r2), "=r"(r3) : "r"(addr))

__device__ __forceinline__ void mma_bf16(float4& d, const uint32_t* a, uint32_t b0, uint32_t b1) {
    asm volatile("mma.sync.aligned.m16n8k16.row.col.f32.bf16.bf16.f32 "
                 "{%0,%1,%2,%3}, {%4,%5,%6,%7}, {%8,%9}, {%0,%1,%2,%3};"
                 : "+f"(d.x), "+f"(d.y), "+f"(d.z), "+f"(d.w)
                 : "r"(a[0]), "r"(a[1]), "r"(a[2]), "r"(a[3]), "r"(b0), "r"(b1));
}

__device__ __forceinline__ void mma_f16(float4& d, const uint32_t* a, uint32_t b0, uint32_t b1) {
    asm volatile("mma.sync.aligned.m16n8k16.row.col.f32.f16.f16.f32 "
                 "{%0,%1,%2,%3}, {%4,%5,%6,%7}, {%8,%9}, {%0,%1,%2,%3};"
                 : "+f"(d.x), "+f"(d.y), "+f"(d.z), "+f"(d.w)
                 : "r"(a[0]), "r"(a[1]), "r"(a[2]), "r"(a[3]), "r"(b0), "r"(b1));
}

__device__ __forceinline__ void cp16(uint32_t s, const void* g) {
    asm volatile("cp.async.cg.shared.global [%0], [%1], 16;" :: "r"(s), "l"(g));
}
__device__ __forceinline__ void cp_commit() {
    asm volatile("cp.async.commit_group;" ::: "memory");
}
template <int N>
__device__ __forceinline__ void cp_wait() {
    asm volatile("cp.async.wait_group %0;" :: "n"(N) : "memory");
}

// fast exp2 on FMA/ALU pipes (no MUFU). Valid for x <= 0; ~4e-5 rel error.
__device__ __forceinline__ float fexp2(float x) {
    x = fmaxf(x, -125.0f);
    const float z = x + 12582912.0f;               // RN to integer (magic)
    const int   n = __float_as_int(z) - 0x4B400000;
    const float f = x - (z - 12582912.0f);          // f in [-0.5, 0.5]
    float p = 0.009618129f;
    p = fmaf(p, f, 0.055504109f);
    p = fmaf(p, f, 0.240226507f);
    p = fmaf(p, f, 0.693147181f);
    p = fmaf(p, f, 1.0f);
    return __int_as_float(__float_as_int(p) + (n << 23));
}

__device__ __forceinline__ unsigned pack_bf2(float a, float b) {
    __nv_bfloat16 ha = __float2bfloat16_rn(a);
    __nv_bfloat16 hb = __float2bfloat16_rn(b);
    return (unsigned)__bfloat16_as_ushort(ha) | ((unsigned)__bfloat16_as_ushort(hb) << 16);
}
__device__ __forceinline__ unsigned pack_hi2(float a, float b, unsigned& lo) {
    __nv_bfloat16 ha = __float2bfloat16_rn(a);
    __nv_bfloat16 hb = __float2bfloat16_rn(b);
    float ra = a - __bfloat162float(ha);
    float rb = b - __bfloat162float(hb);
    lo = pack_bf2(ra, rb);
    return (unsigned)__bfloat16_as_ushort(ha) | ((unsigned)__bfloat16_as_ushort(hb) << 16);
}
__device__ __forceinline__ unsigned pack_h2(float a, float b) {
    __half2 h = __floats2half2_rn(a, b);
    return *(unsigned*)&h;
}

// ============================================================================
// fused split: z<4 -> weights, z==4 -> x
// ============================================================================
__global__ __launch_bounds__(256)
void split5_kernel(const float4* __restrict__ w0, const float4* __restrict__ w1,
                   const float4* __restrict__ w2, const float4* __restrict__ w3,
                   const float4* __restrict__ x)
{
    const int z = blockIdx.z;
    const float4* src;
    uint2 *hi, *lo;
    int n4;
    if (z < 4) {
        src = (z == 0) ? w0 : (z == 1) ? w1 : (z == 2) ? w2 : w3;
        hi = (uint2*)(g_whi + (size_t)z * DM * DM);
        lo = (uint2*)(g_wlo + (size_t)z * DM * DM);
        n4 = DM * DM / 4;
    } else {
        src = x;
        hi = (uint2*)g_xhi;
        lo = (uint2*)g_xlo;
        n4 = SQ * DM / 4;
    }
    for (int i = blockIdx.x * blockDim.x + threadIdx.x; i < n4;
         i += gridDim.x * blockDim.x) {
        float4 v = src[i];
        unsigned l0, l1;
        unsigned h0 = pack_hi2(v.x, v.y, l0);
        unsigned h1 = pack_hi2(v.z, v.w, l1);
        hi[i] = make_uint2(h0, h1);
        lo[i] = make_uint2(l0, l1);
    }
}

// ============================================================================
// GEMM via mma.sync, bf16 hi/lo 3-term. 128x128 tile, K-chunk 32,
// ring-3 cp.async pipeline, XOR-swizzled smem, ONE sync per chunk.
// ============================================================================
#define G_STG 32768
#define GA_HI 0
#define GA_LO 8192
#define GB_HI 16384
#define GB_LO 24576

__device__ __forceinline__ uint32_t gswz(int row, int chunk) {
    return (uint32_t)(row * 64 + ((chunk ^ ((row >> 1) & 3)) << 4));
}

template <int MODE>
__global__ __launch_bounds__(256, 2)
void gemm_mma(const __nv_bfloat16* __restrict__ Ahi,
              const __nv_bfloat16* __restrict__ Alo,
              int wslot,
              const float* __restrict__ b0p, const float* __restrict__ b1p,
              const float* __restrict__ b2p,
              float* __restrict__ out)
{
    extern __shared__ __align__(16) char smem[];
    const uint32_t sb = smem_u32(smem);

    const int t = threadIdx.x;
    const int warp = t >> 5, lane = t & 31;
    const int warpM = warp >> 2, warpN = warp & 3;
    const int z = blockIdx.z;
    const int blockM = blockIdx.y * 128;
    const int blockN = blockIdx.x * 128;

    const __nv_bfloat16* Whi = g_whi + (size_t)(wslot + z) * DM * DM;
    const __nv_bfloat16* Wlo = g_wlo + (size_t)(wslot + z) * DM * DM;
    const float* bias = (z == 0) ? b0p : ((z == 1) ? b1p : b2p);

    const int lr = t >> 2;
    const int lch = t & 3;

    float4 acc[4][4];
#pragma unroll
    for (int i = 0; i < 4; i++)
#pragma unroll
        for (int j = 0; j < 4; j++) acc[i][j] = make_float4(0.f, 0.f, 0.f, 0.f);

#pragma unroll
    for (int pc = 0; pc < 2; pc++) {
        const uint32_t stg = sb + pc * G_STG;
        const int kc = pc * 32 + lch * 8;
#pragma unroll
        for (int it = 0; it < 2; it++) {
            const int r = lr + it * 64;
            const uint32_t so = gswz(r, lch);
            cp16(stg + GA_HI + so, Ahi + (size_t)(blockM + r) * DM + kc);
            cp16(stg + GA_LO + so, Alo + (size_t)(blockM + r) * DM + kc);
            cp16(stg + GB_HI + so, Whi + (size_t)(blockN + r) * DM + kc);
            cp16(stg + GB_LO + so, Wlo + (size_t)(blockN + r) * DM + kc);
        }
        cp_commit();
    }

    for (int c = 0; c < 32; c++) {
        cp_wait<1>();
        __syncthreads();

        const uint32_t stg = sb + (c % 3) * G_STG;
#pragma unroll
        for (int ks = 0; ks < 2; ks++) {
            const int chA = 2 * ks + (lane >> 4);
            const int chB = 2 * ks + ((lane >> 3) & 1);

            uint32_t a[4][4];
#pragma unroll
            for (int i = 0; i < 4; i++) {
                const int arow = warpM * 64 + i * 16 + (lane & 15);
                LDSM_X4(a[i][0], a[i][1], a[i][2], a[i][3],
                        stg + GA_HI + gswz(arow, chA));
            }
            uint32_t bh[4][2], bl[4][2];
#pragma unroll
            for (int p = 0; p < 2; p++) {
                const int brow = warpN * 32 + p * 16 + ((lane >> 4) * 8) + (lane & 7);
                uint32_t m0, m1, m2, m3;
                LDSM_X4(m0, m1, m2, m3, stg + GB_HI + gswz(brow, chB));
                bh[2 * p][0] = m0; bh[2 * p][1] = m1; bh[2 * p + 1][0] = m2; bh[2 * p + 1][1] = m3;
                LDSM_X4(m0, m1, m2, m3, stg + GB_LO + gswz(brow, chB));
                bl[2 * p][0] = m0; bl[2 * p][1] = m1; bl[2 * p + 1][0] = m2; bl[2 * p + 1][1] = m3;
            }
#pragma unroll
            for (int i = 0; i < 4; i++)
#pragma unroll
                for (int j = 0; j < 4; j++) {
                    mma_bf16(acc[i][j], a[i], bh[j][0], bh[j][1]);
                    mma_bf16(acc[i][j], a[i], bl[j][0], bl[j][1]);
                }
#pragma unroll
            for (int i = 0; i < 4; i++) {
                const int arow = warpM * 64 + i * 16 + (lane & 15);
                LDSM_X4(a[i][0], a[i][1], a[i][2], a[i][3],
                        stg + GA_LO + gswz(arow, chA));
            }
#pragma unroll
            for (int i = 0; i < 4; i++)
#pragma unroll
                for (int j = 0; j < 4; j++)
                    mma_bf16(acc[i][j], a[i], bh[j][0], bh[j][1]);
        }

        if (c + 2 < 32) {
            const uint32_t stg2 = sb + ((c + 2) % 3) * G_STG;
            const int kc = (c + 2) * 32 + lch * 8;
#pragma unroll
            for (int it = 0; it < 2; it++) {
                const int r = lr + it * 64;
                const uint32_t so = gswz(r, lch);
                cp16(stg2 + GA_HI + so, Ahi + (size_t)(blockM + r) * DM + kc);
                cp16(stg2 + GA_LO + so, Alo + (size_t)(blockM + r) * DM + kc);
                cp16(stg2 + GB_HI + so, Whi + (size_t)(blockN + r) * DM + kc);
                cp16(stg2 + GB_LO + so, Wlo + (size_t)(blockN + r) * DM + kc);
            }
        }
        cp_commit();
    }

    const float sc = (MODE == 0 && z == 0) ? (QSCALE * LOG2E) : 1.f;
#pragma unroll
    for (int i = 0; i < 4; i++) {
#pragma unroll
        for (int j = 0; j < 4; j++) {
            const int row0 = blockM + warpM * 64 + i * 16 + (lane >> 2);
            const int row1 = row0 + 8;
            const int col = blockN + warpN * 32 + j * 8 + (lane & 3) * 2;
            const float bx = bias[col], by = bias[col + 1];
            const float vx = (acc[i][j].x + bx) * sc;
            const float vy = (acc[i][j].y + by) * sc;
            const float vz = (acc[i][j].z + bx) * sc;
            const float vw = (acc[i][j].w + by) * sc;
            if (MODE == 1) {
                *(float2*)(out + (size_t)row0 * DM + col) = make_float2(vx, vy);
                *(float2*)(out + (size_t)row1 * DM + col) = make_float2(vz, vw);
            } else {
                const int hh = col >> 6, d = col & 63;
                const size_t a0 = (size_t)hh * SQ * HS + (size_t)row0 * HS + d;
                const size_t a1 = (size_t)hh * SQ * HS + (size_t)row1 * HS + d;
                if (z < 2) {
                    __nv_bfloat16* harr = z ? g_khi : g_qhi;
                    __nv_bfloat16* larr = z ? g_klo : g_qlo;
                    unsigned l0, l1;
                    unsigned h0 = pack_hi2(vx, vy, l0);
                    unsigned h1 = pack_hi2(vz, vw, l1);
                    *(uint32_t*)(harr + a0) = h0;
                    *(uint32_t*)(larr + a0) = l0;
                    *(uint32_t*)(harr + a1) = h1;
                    *(uint32_t*)(larr + a1) = l1;
                } else {
                    *(uint32_t*)(g_vhi + a0) = pack_h2(vx, vy);
                    *(uint32_t*)(g_vhi + a1) = pack_h2(vz, vw);
                }
            }
        }
    }
}

// ============================================================================
// Flash attention, ring-3 cp.async, ONE sync per k-tile, FMA-pipe exp2.
// ============================================================================
#define GSTB 144
#define KVBUF 27648
#define OFF_KHI 0
#define OFF_KLO 9216
#define OFF_VHI 18432
#define ATTN_SMEM_TOT (3 * KVBUF)

__global__ __launch_bounds__(256, 2)
void attn_mma()
{
    extern __shared__ __align__(16) char smem[];
    const uint32_t sb = smem_u32(smem);

    const int h  = blockIdx.y;
    const int qb = gridDim.x - 1 - blockIdx.x;
    const int t = threadIdx.x;
    const int warp = t >> 5, lane = t & 31;

    const size_t hbase = (size_t)h * SQ * HS;

#pragma unroll
    for (int it = 0; it < 4; it++) {
        const int idx = it * 256 + t;
        const int r = idx >> 3;
        const int c8 = (idx & 7) * 8;
        const size_t g = hbase + (size_t)(qb * 128 + r) * HS + c8;
        const uint32_t so = r * GSTB + c8 * 2;
        *(uint4*)(smem + so) = *(const uint4*)(g_qhi + g);
        *(uint4*)(smem + 18432 + so) = *(const uint4*)(g_qlo + g);
    }
    __syncthreads();

    uint32_t qh[4][4], ql[4][4];
#pragma unroll
    for (int ks = 0; ks < 4; ks++) {
        const uint32_t ro = (warp * 16 + (lane & 15)) * GSTB + (ks * 16 + (lane >> 4) * 8) * 2;
        LDSM_X4(qh[ks][0], qh[ks][1], qh[ks][2], qh[ks][3], sb + ro);
        LDSM_X4(ql[ks][0], ql[ks][1], ql[ks][2], ql[ks][3], sb + 18432 + ro);
    }
    __syncthreads();

    const int nkt = 2 * qb + 2;

#pragma unroll
    for (int i = 0; i < 2; i++) {
        const uint32_t bufb = sb + i * KVBUF;
#pragma unroll
        for (int it = 0; it < 2; it++) {
            const int idx = it * 256 + t;
            const int r = idx >> 3;
            const int c8 = (idx & 7) * 8;
            const size_t g = hbase + (size_t)(i * 64 + r) * HS + c8;
            const uint32_t so = r * GSTB + c8 * 2;
            cp16(bufb + OFF_KHI + so, g_khi + g);
            cp16(bufb + OFF_KLO + so, g_klo + g);
            cp16(bufb + OFF_VHI + so, g_vhi + g);
        }
        cp_commit();
    }

    float4 o[8];
#pragma unroll
    for (int f = 0; f < 8; f++) o[f] = make_float4(0.f, 0.f, 0.f, 0.f);
    float m0 = -1e30f, m1 = -1e30f, l0s = 0.f, l1s = 0.f;

    for (int kt = 0; kt < nkt; kt++) {
        cp_wait<1>();
        __syncthreads();

        const uint32_t kvb = sb + (kt % 3) * KVBUF;

        float4 s[8];
#pragma unroll
        for (int f = 0; f < 8; f++) s[f] = make_float4(0.f, 0.f, 0.f, 0.f);

#pragma unroll
        for (int ks = 0; ks < 4; ks++) {
            const uint32_t bcol = (ks * 16 + ((lane >> 3) & 1) * 8) * 2;
#pragma unroll
            for (int p = 0; p < 4; p++) {
                const uint32_t brow = (p * 16 + ((lane >> 4) * 8) + (lane & 7)) * GSTB;
                uint32_t h0, h1, h2, h3, l0, l1, l2, l3;
                LDSM_X4(h0, h1, h2, h3, kvb + OFF_KHI + brow + bcol);
                LDSM_X4(l0, l1, l2, l3, kvb + OFF_KLO + brow + bcol);
                mma_bf16(s[2 * p],     qh[ks], h0, h1);
                mma_bf16(s[2 * p],     qh[ks], l0, l1);
                mma_bf16(s[2 * p],     ql[ks], h0, h1);
                mma_bf16(s[2 * p + 1], qh[ks], h2, h3);
                mma_bf16(s[2 * p + 1], qh[ks], l2, l3);
                mma_bf16(s[2 * p + 1], ql[ks], h2, h3);
            }
        }

        if (kt * 64 + 63 > qb * 128 + warp * 16) {
            const int q0 = qb * 128 + warp * 16 + (lane >> 2);
            const int q1 = q0 + 8;
#pragma unroll
            for (int f = 0; f < 8; f++) {
                const int kc = kt * 64 + f * 8 + (lane & 3) * 2;
                if (kc > q0)     s[f].x = NEG;
                if (kc + 1 > q0) s[f].y = NEG;
                if (kc > q1)     s[f].z = NEG;
                if (kc + 1 > q1) s[f].w = NEG;
            }
        }

        float rmax0 = NEG, rmax1 = NEG;
#pragma unroll
        for (int f = 0; f < 8; f++) {
            rmax0 = fmaxf(rmax0, fmaxf(s[f].x, s[f].y));
            rmax1 = fmaxf(rmax1, fmaxf(s[f].z, s[f].w));
        }
        rmax0 = fmaxf(rmax0, __shfl_xor_sync(0xffffffffu, rmax0, 1));
        rmax0 = fmaxf(rmax0, __shfl_xor_sync(0xffffffffu, rmax0, 2));
        rmax1 = fmaxf(rmax1, __shfl_xor_sync(0xffffffffu, rmax1, 1));
        rmax1 = fmaxf(rmax1, __shfl_xor_sync(0xffffffffu, rmax1, 2));

        const float mn0 = fmaxf(m0, rmax0);
        const float mn1 = fmaxf(m1, rmax1);
        const float c0 = fexp2(m0 - mn0);
        const float c1 = fexp2(m1 - mn1);

        float rs0 = 0.f, rs1 = 0.f;
#pragma unroll
        for (int f = 0; f < 8; f++) {
            s[f].x = fexp2(s[f].x - mn0);
            s[f].y = fexp2(s[f].y - mn0);
            s[f].z = fexp2(s[f].z - mn1);
            s[f].w = fexp2(s[f].w - mn1);
            rs0 += s[f].x + s[f].y;
            rs1 += s[f].z + s[f].w;
        }
        rs0 += __shfl_xor_sync(0xffffffffu, rs0, 1);
        rs0 += __shfl_xor_sync(0xffffffffu, rs0, 2);
        rs1 += __shfl_xor_sync(0xffffffffu, rs1, 1);
        rs1 += __shfl_xor_sync(0xffffffffu, rs1, 2);

        l0s = l0s * c0 + rs0;
        l1s = l1s * c1 + rs1;
        m0 = mn0; m1 = mn1;
#pragma unroll
        for (int f = 0; f < 8; f++) {
            o[f].x *= c0; o[f].y *= c0; o[f].z *= c1; o[f].w *= c1;
        }

#pragma unroll
        for (int ks = 0; ks < 4; ks++) {
            uint32_t ap[4];
            ap[0] = pack_h2(s[2 * ks].x,     s[2 * ks].y);
            ap[1] = pack_h2(s[2 * ks].z,     s[2 * ks].w);
            ap[2] = pack_h2(s[2 * ks + 1].x, s[2 * ks + 1].y);
            ap[3] = pack_h2(s[2 * ks + 1].z, s[2 * ks + 1].w);

            const uint32_t vrow = (ks * 16 + (lane & 7) + ((lane >> 3) & 1) * 8) * GSTB;
#pragma unroll
            for (int g = 0; g < 4; g++) {
                const uint32_t vcol = (g * 16 + (lane >> 4) * 8) * 2;
                uint32_t v0, v1, v2, v3;
                LDSM_X4_T(v0, v1, v2, v3, kvb + OFF_VHI + vrow + vcol);
                mma_f16(o[2 * g],     ap, v0, v1);
                mma_f16(o[2 * g + 1], ap, v2, v3);
            }
        }

        if (kt + 2 < nkt) {
            const uint32_t bufb = sb + ((kt + 2) % 3) * KVBUF;
#pragma unroll
            for (int it = 0; it < 2; it++) {
                const int idx = it * 256 + t;
                const int r = idx >> 3;
                const int c8 = (idx & 7) * 8;
                const size_t g = hbase + (size_t)((kt + 2) * 64 + r) * HS + c8;
                const uint32_t so = r * GSTB + c8 * 2;
                cp16(bufb + OFF_KHI + so, g_khi + g);
                cp16(bufb + OFF_KLO + so, g_klo + g);
                cp16(bufb + OFF_VHI + so, g_vhi + g);
            }
        }
        cp_commit();
    }

    const float inv0 = 1.f / l0s;
    const float inv1 = 1.f / l1s;
    const int r0 = qb * 128 + warp * 16 + (lane >> 2);
    const int r1 = r0 + 8;
#pragma unroll
    for (int f = 0; f < 8; f++) {
        const int col = h * HS + f * 8 + (lane & 3) * 2;
        unsigned l0p, l1p;
        unsigned h0p = pack_hi2(o[f].x * inv0, o[f].y * inv0, l0p);
        unsigned h1p = pack_hi2(o[f].z * inv1, o[f].w * inv1, l1p);
        *(uint32_t*)(g_xhi + (size_t)r0 * DM + col) = h0p;
        *(uint32_t*)(g_xlo + (size_t)r0 * DM + col) = l0p;
        *(uint32_t*)(g_xhi + (size_t)r1 * DM + col) = h1p;
        *(uint32_t*)(g_xlo + (size_t)r1 * DM + col) = l1p;
    }
}

// ============================================================================
// launch
// ============================================================================
extern "C" void kernel_launch(void* const* d_in, const int* in_sizes, int n_in,
                              void* d_out, int out_size)
{
    (void)in_sizes; (void)n_in; (void)out_size;
    const float* x  = (const float*)d_in[0];
    const float* wq = (const float*)d_in[1];
    const float* bq = (const float*)d_in[2];
    const float* wk = (const float*)d_in[3];
    const float* bk = (const float*)d_in[4];
    const float* wv = (const float*)d_in[5];
    const float* bv = (const float*)d_in[6];
    const float* wo = (const float*)d_in[7];
    const float* bo = (const float*)d_in[8];
    float* out = (float*)d_out;

    __nv_bfloat16 *xhi, *xlo;
    cudaGetSymbolAddress((void**)&xhi, g_xhi);
    cudaGetSymbolAddress((void**)&xlo, g_xlo);

    const int GEMM_SMEM = 3 * G_STG;
    cudaFuncSetAttribute(gemm_mma<0>,
                         cudaFuncAttributeMaxDynamicSharedMemorySize, GEMM_SMEM);
    cudaFuncSetAttribute(gemm_mma<1>,
                         cudaFuncAttributeMaxDynamicSharedMemorySize, GEMM_SMEM);
    cudaFuncSetAttribute(attn_mma,
                         cudaFuncAttributeMaxDynamicSharedMemorySize, ATTN_SMEM_TOT);

    split5_kernel<<<dim3(512, 1, 5), 256>>>((const float4*)wq, (const float4*)wk,
                                            (const float4*)wv, (const float4*)wo,
                                            (const float4*)x);

    gemm_mma<0><<<dim3(DM / 128, SQ / 128, 3), 256, GEMM_SMEM>>>(
        xhi, xlo, 0, bq, bk, bv, nullptr);

    attn_mma<<<dim3(SQ / 128, NH), 256, ATTN_SMEM_TOT>>>();

    gemm_mma<1><<<dim3(DM / 128, SQ / 128, 1), 256, GEMM_SMEM>>>(
        xhi, xlo, 3, bo, bo, bo, out);
}

// round 11
// speedup vs baseline: 1.1958x; 1.1958x over previous
#include <cuda_runtime.h>
#include <cuda_bf16.h>
#include <cuda_fp16.h>
#include <cstdint>

#define SQ 4096
#define DM 1024
#define NH 16
#define HS 64
#define QSCALE 0.125f
#define LOG2E 1.4426950408889634f
#define NEG -1e9f

// -------- scratch (no allocations allowed) --------
__device__ __align__(16) __nv_bfloat16 g_xhi[SQ * DM];
__device__ __align__(16) __nv_bfloat16 g_xlo[SQ * DM];
__device__ __align__(16) __nv_bfloat16 g_whi[4 * DM * DM];
__device__ __align__(16) __nv_bfloat16 g_wlo[4 * DM * DM];
__device__ __align__(16) __half g_qhi[NH * SQ * HS];   // fp16 hi (exp2-domain scaled)
__device__ __align__(16) __half g_qlo[NH * SQ * HS];   // fp16 lo residual
__device__ __align__(16) __half g_khi[NH * SQ * HS];   // fp16 single
__device__ __align__(16) __half g_vhi[NH * SQ * HS];   // fp16 single

// ============================================================================
// helpers
// ============================================================================
__device__ __forceinline__ uint32_t smem_u32(const void* p) {
    uint32_t a;
    asm("{ .reg .u64 t; cvta.to.shared.u64 t, %1; cvt.u32.u64 %0, t; }" : "=r"(a) : "l"(p));
    return a;
}

#define LDSM_X4(r0, r1, r2, r3, addr) \
    asm volatile("ldmatrix.sync.aligned.m8n8.x4.shared.b16 {%0,%1,%2,%3}, [%4];" \
                 : "=r"(r0), "=r"(r1), "=r"(r2), "=r"(r3) : "r"(addr))

#define LDSM_X4_T(r0, r1, r2, r3, addr) \
    asm volatile("ldmatrix.sync.aligned.m8n8.x4.trans.shared.b16 {%0,%1,%2,%3}, [%4];" \
                 : "=r"(r0), "=r"(r1), "=r"(r2), "=r"(r3) : "r"(addr))

__device__ __forceinline__ void mma_bf16(float4& d, const uint32_t* a, uint32_t b0, uint32_t b1) {
    asm volatile("mma.sync.aligned.m16n8k16.row.col.f32.bf16.bf16.f32 "
                 "{%0,%1,%2,%3}, {%4,%5,%6,%7}, {%8,%9}, {%0,%1,%2,%3};"
                 : "+f"(d.x), "+f"(d.y), "+f"(d.z), "+f"(d.w)
                 : "r"(a[0]), "r"(a[1]), "r"(a[2]), "r"(a[3]), "r"(b0), "r"(b1));
}

__device__ __forceinline__ void mma_f16(float4& d, const uint32_t* a, uint32_t b0, uint32_t b1) {
    asm volatile("mma.sync.aligned.m16n8k16.row.col.f32.f16.f16.f32 "
                 "{%0,%1,%2,%3}, {%4,%5,%6,%7}, {%8,%9}, {%0,%1,%2,%3};"
                 : "+f"(d.x), "+f"(d.y), "+f"(d.z), "+f"(d.w)
                 : "r"(a[0]), "r"(a[1]), "r"(a[2]), "r"(a[3]), "r"(b0), "r"(b1));
}

__device__ __forceinline__ void cp16(uint32_t s, const void* g) {
    asm volatile("cp.async.cg.shared.global [%0], [%1], 16;" :: "r"(s), "l"(g));
}
__device__ __forceinline__ void cp_commit() {
    asm volatile("cp.async.commit_group;" ::: "memory");
}
template <int N>
__device__ __forceinline__ void cp_wait() {
    asm volatile("cp.async.wait_group %0;" :: "n"(N) : "memory");
}

__device__ __forceinline__ unsigned pack_bf2(float a, float b) {
    __nv_bfloat16 ha = __float2bfloat16_rn(a);
    __nv_bfloat16 hb = __float2bfloat16_rn(b);
    return (unsigned)__bfloat16_as_ushort(ha) | ((unsigned)__bfloat16_as_ushort(hb) << 16);
}
__device__ __forceinline__ unsigned pack_hi2(float a, float b, unsigned& lo) {
    __nv_bfloat16 ha = __float2bfloat16_rn(a);
    __nv_bfloat16 hb = __float2bfloat16_rn(b);
    float ra = a - __bfloat162float(ha);
    float rb = b - __bfloat162float(hb);
    lo = pack_bf2(ra, rb);
    return (unsigned)__bfloat16_as_ushort(ha) | ((unsigned)__bfloat16_as_ushort(hb) << 16);
}
__device__ __forceinline__ unsigned pack_h2(float a, float b) {
    __half2 h = __floats2half2_rn(a, b);
    return *(unsigned*)&h;
}
__device__ __forceinline__ unsigned pack_h2_hi(float a, float b, unsigned& lo) {
    __half ha = __float2half_rn(a);
    __half hb = __float2half_rn(b);
    float ra = a - __half2float(ha);
    float rb = b - __half2float(hb);
    lo = pack_h2(ra, rb);
    __half2 h2v = __halves2half2(ha, hb);
    return *(unsigned*)&h2v;
}

// ============================================================================
// fused split: z<4 -> weights, z==4 -> x
// ============================================================================
__global__ __launch_bounds__(256)
void split5_kernel(const float4* __restrict__ w0, const float4* __restrict__ w1,
                   const float4* __restrict__ w2, const float4* __restrict__ w3,
                   const float4* __restrict__ x)
{
    const int z = blockIdx.z;
    const float4* src;
    uint2 *hi, *lo;
    int n4;
    if (z < 4) {
        src = (z == 0) ? w0 : (z == 1) ? w1 : (z == 2) ? w2 : w3;
        hi = (uint2*)(g_whi + (size_t)z * DM * DM);
        lo = (uint2*)(g_wlo + (size_t)z * DM * DM);
        n4 = DM * DM / 4;
    } else {
        src = x;
        hi = (uint2*)g_xhi;
        lo = (uint2*)g_xlo;
        n4 = SQ * DM / 4;
    }
    for (int i = blockIdx.x * blockDim.x + threadIdx.x; i < n4;
         i += gridDim.x * blockDim.x) {
        float4 v = src[i];
        unsigned l0, l1;
        unsigned h0 = pack_hi2(v.x, v.y, l0);
        unsigned h1 = pack_hi2(v.z, v.w, l1);
        hi[i] = make_uint2(h0, h1);
        lo[i] = make_uint2(l0, l1);
    }
}

// ============================================================================
// GEMM via mma.sync, bf16 hi/lo 3-term. 128x128 tile, K-chunk 32,
// ring-3 cp.async pipeline, XOR-swizzled smem, ONE sync per chunk.
// ============================================================================
#define G_STG 32768
#define GA_HI 0
#define GA_LO 8192
#define GB_HI 16384
#define GB_LO 24576

__device__ __forceinline__ uint32_t gswz(int row, int chunk) {
    return (uint32_t)(row * 64 + ((chunk ^ ((row >> 1) & 3)) << 4));
}

template <int MODE>
__global__ __launch_bounds__(256, 2)
void gemm_mma(const __nv_bfloat16* __restrict__ Ahi,
              const __nv_bfloat16* __restrict__ Alo,
              int wslot,
              const float* __restrict__ b0p, const float* __restrict__ b1p,
              const float* __restrict__ b2p,
              float* __restrict__ out)
{
    extern __shared__ __align__(16) char smem[];
    const uint32_t sb = smem_u32(smem);

    const int t = threadIdx.x;
    const int warp = t >> 5, lane = t & 31;
    const int warpM = warp >> 2, warpN = warp & 3;
    const int z = blockIdx.z;
    const int blockM = blockIdx.y * 128;
    const int blockN = blockIdx.x * 128;

    const __nv_bfloat16* Whi = g_whi + (size_t)(wslot + z) * DM * DM;
    const __nv_bfloat16* Wlo = g_wlo + (size_t)(wslot + z) * DM * DM;
    const float* bias = (z == 0) ? b0p : ((z == 1) ? b1p : b2p);

    const int lr = t >> 2;
    const int lch = t & 3;

    float4 acc[4][4];
#pragma unroll
    for (int i = 0; i < 4; i++)
#pragma unroll
        for (int j = 0; j < 4; j++) acc[i][j] = make_float4(0.f, 0.f, 0.f, 0.f);

#pragma unroll
    for (int pc = 0; pc < 2; pc++) {
        const uint32_t stg = sb + pc * G_STG;
        const int kc = pc * 32 + lch * 8;
#pragma unroll
        for (int it = 0; it < 2; it++) {
            const int r = lr + it * 64;
            const uint32_t so = gswz(r, lch);
            cp16(stg + GA_HI + so, Ahi + (size_t)(blockM + r) * DM + kc);
            cp16(stg + GA_LO + so, Alo + (size_t)(blockM + r) * DM + kc);
            cp16(stg + GB_HI + so, Whi + (size_t)(blockN + r) * DM + kc);
            cp16(stg + GB_LO + so, Wlo + (size_t)(blockN + r) * DM + kc);
        }
        cp_commit();
    }

    for (int c = 0; c < 32; c++) {
        cp_wait<1>();
        __syncthreads();

        const uint32_t stg = sb + (c % 3) * G_STG;
#pragma unroll
        for (int ks = 0; ks < 2; ks++) {
            const int chA = 2 * ks + (lane >> 4);
            const int chB = 2 * ks + ((lane >> 3) & 1);

            uint32_t a[4][4];
#pragma unroll
            for (int i = 0; i < 4; i++) {
                const int arow = warpM * 64 + i * 16 + (lane & 15);
                LDSM_X4(a[i][0], a[i][1], a[i][2], a[i][3],
                        stg + GA_HI + gswz(arow, chA));
            }
            uint32_t bh[4][2], bl[4][2];
#pragma unroll
            for (int p = 0; p < 2; p++) {
                const int brow = warpN * 32 + p * 16 + ((lane >> 4) * 8) + (lane & 7);
                uint32_t m0, m1, m2, m3;
                LDSM_X4(m0, m1, m2, m3, stg + GB_HI + gswz(brow, chB));
                bh[2 * p][0] = m0; bh[2 * p][1] = m1; bh[2 * p + 1][0] = m2; bh[2 * p + 1][1] = m3;
                LDSM_X4(m0, m1, m2, m3, stg + GB_LO + gswz(brow, chB));
                bl[2 * p][0] = m0; bl[2 * p][1] = m1; bl[2 * p + 1][0] = m2; bl[2 * p + 1][1] = m3;
            }
#pragma unroll
            for (int i = 0; i < 4; i++)
#pragma unroll
                for (int j = 0; j < 4; j++) {
                    mma_bf16(acc[i][j], a[i], bh[j][0], bh[j][1]);
                    mma_bf16(acc[i][j], a[i], bl[j][0], bl[j][1]);
                }
#pragma unroll
            for (int i = 0; i < 4; i++) {
                const int arow = warpM * 64 + i * 16 + (lane & 15);
                LDSM_X4(a[i][0], a[i][1], a[i][2], a[i][3],
                        stg + GA_LO + gswz(arow, chA));
            }
#pragma unroll
            for (int i = 0; i < 4; i++)
#pragma unroll
                for (int j = 0; j < 4; j++)
                    mma_bf16(acc[i][j], a[i], bh[j][0], bh[j][1]);
        }

        if (c + 2 < 32) {
            const uint32_t stg2 = sb + ((c + 2) % 3) * G_STG;
            const int kc = (c + 2) * 32 + lch * 8;
#pragma unroll
            for (int it = 0; it < 2; it++) {
                const int r = lr + it * 64;
                const uint32_t so = gswz(r, lch);
                cp16(stg2 + GA_HI + so, Ahi + (size_t)(blockM + r) * DM + kc);
                cp16(stg2 + GA_LO + so, Alo + (size_t)(blockM + r) * DM + kc);
                cp16(stg2 + GB_HI + so, Whi + (size_t)(blockN + r) * DM + kc);
                cp16(stg2 + GB_LO + so, Wlo + (size_t)(blockN + r) * DM + kc);
            }
        }
        cp_commit();
    }

    // epilogue (q scaled into exp2 domain, split fp16 hi/lo; k,v single fp16)
    const float sc = (MODE == 0 && z == 0) ? (QSCALE * LOG2E) : 1.f;
#pragma unroll
    for (int i = 0; i < 4; i++) {
#pragma unroll
        for (int j = 0; j < 4; j++) {
            const int row0 = blockM + warpM * 64 + i * 16 + (lane >> 2);
            const int row1 = row0 + 8;
            const int col = blockN + warpN * 32 + j * 8 + (lane & 3) * 2;
            const float bx = bias[col], by = bias[col + 1];
            const float vx = (acc[i][j].x + bx) * sc;
            const float vy = (acc[i][j].y + by) * sc;
            const float vz = (acc[i][j].z + bx) * sc;
            const float vw = (acc[i][j].w + by) * sc;
            if (MODE == 1) {
                *(float2*)(out + (size_t)row0 * DM + col) = make_float2(vx, vy);
                *(float2*)(out + (size_t)row1 * DM + col) = make_float2(vz, vw);
            } else {
                const int hh = col >> 6, d = col & 63;
                const size_t a0 = (size_t)hh * SQ * HS + (size_t)row0 * HS + d;
                const size_t a1 = (size_t)hh * SQ * HS + (size_t)row1 * HS + d;
                if (z == 0) {
                    unsigned l0, l1;
                    unsigned h0 = pack_h2_hi(vx, vy, l0);
                    unsigned h1 = pack_h2_hi(vz, vw, l1);
                    *(uint32_t*)(g_qhi + a0) = h0;
                    *(uint32_t*)(g_qlo + a0) = l0;
                    *(uint32_t*)(g_qhi + a1) = h1;
                    *(uint32_t*)(g_qlo + a1) = l1;
                } else if (z == 1) {
                    *(uint32_t*)(g_khi + a0) = pack_h2(vx, vy);
                    *(uint32_t*)(g_khi + a1) = pack_h2(vz, vw);
                } else {
                    *(uint32_t*)(g_vhi + a0) = pack_h2(vx, vy);
                    *(uint32_t*)(g_vhi + a1) = pack_h2(vz, vw);
                }
            }
        }
    }
}

// ============================================================================
// Flash attention, ring-3 cp.async, ONE sync per k-tile, exp2f softmax.
// S = Q(fp16 hi/lo, 2 terms) x K(fp16).  PV = P fp16 x V fp16.
// KV buffer per tile: K 9216 + V 9216 = 18432; ring-3 = 55296.
// ============================================================================
#define GSTB 144
#define KVBUF 18432
#define OFF_KHI 0
#define OFF_VHI 9216
#define ATTN_SMEM_TOT (3 * KVBUF)   // 55296

__global__ __launch_bounds__(256, 2)
void attn_mma()
{
    extern __shared__ __align__(16) char smem[];
    const uint32_t sb = smem_u32(smem);

    const int h  = blockIdx.y;
    const int qb = gridDim.x - 1 - blockIdx.x;
    const int t = threadIdx.x;
    const int warp = t >> 5, lane = t & 31;

    const size_t hbase = (size_t)h * SQ * HS;

    // ---- stage Q tile (128 rows, fp16 hi|lo) — region reused by ring after ----
#pragma unroll
    for (int it = 0; it < 4; it++) {
        const int idx = it * 256 + t;
        const int r = idx >> 3;
        const int c8 = (idx & 7) * 8;
        const size_t g = hbase + (size_t)(qb * 128 + r) * HS + c8;
        const uint32_t so = r * GSTB + c8 * 2;
        *(uint4*)(smem + so) = *(const uint4*)(g_qhi + g);
        *(uint4*)(smem + 18432 + so) = *(const uint4*)(g_qlo + g);
    }
    __syncthreads();

    uint32_t qh[4][4], ql[4][4];
#pragma unroll
    for (int ks = 0; ks < 4; ks++) {
        const uint32_t ro = (warp * 16 + (lane & 15)) * GSTB + (ks * 16 + (lane >> 4) * 8) * 2;
        LDSM_X4(qh[ks][0], qh[ks][1], qh[ks][2], qh[ks][3], sb + ro);
        LDSM_X4(ql[ks][0], ql[ks][1], ql[ks][2], ql[ks][3], sb + 18432 + ro);
    }
    __syncthreads();   // Q consumed before ring reuse

    const int nkt = 2 * qb + 2;

#pragma unroll
    for (int i = 0; i < 2; i++) {
        const uint32_t bufb = sb + i * KVBUF;
#pragma unroll
        for (int it = 0; it < 1; it++) { }
        // K+V tile: 64 rows x 128B each -> 512 cp16 per tile over 256 threads
        {
            const int idx = t;                 // 0..255 -> K rows
            const int r = idx >> 2;            // 0..63
            const int c8 = (idx & 3) * 16;     // 0,16,32,48 (fp16 elems)
            const size_t g = hbase + (size_t)(i * 64 + r) * HS + c8;
            const uint32_t so = r * GSTB + c8 * 2;
            cp16(bufb + OFF_KHI + so,      g_khi + g);
            cp16(bufb + OFF_KHI + so + 16, g_khi + g + 8);
            cp16(bufb + OFF_VHI + so,      g_vhi + g);
            cp16(bufb + OFF_VHI + so + 16, g_vhi + g + 8);
        }
        cp_commit();
    }

    float4 o[8];
#pragma unroll
    for (int f = 0; f < 8; f++) o[f] = make_float4(0.f, 0.f, 0.f, 0.f);
    float m0 = -1e30f, m1 = -1e30f, l0s = 0.f, l1s = 0.f;

    for (int kt = 0; kt < nkt; kt++) {
        cp_wait<1>();
        __syncthreads();

        const uint32_t kvb = sb + (kt % 3) * KVBUF;

        // ---- S = Q K^T (fp16, 2 terms) ----
        float4 s[8];
#pragma unroll
        for (int f = 0; f < 8; f++) s[f] = make_float4(0.f, 0.f, 0.f, 0.f);

#pragma unroll
        for (int ks = 0; ks < 4; ks++) {
            const uint32_t bcol = (ks * 16 + ((lane >> 3) & 1) * 8) * 2;
#pragma unroll
            for (int p = 0; p < 4; p++) {
                const uint32_t brow = (p * 16 + ((lane >> 4) * 8) + (lane & 7)) * GSTB;
                uint32_t k0, k1, k2, k3;
                LDSM_X4(k0, k1, k2, k3, kvb + OFF_KHI + brow + bcol);
                mma_f16(s[2 * p],     qh[ks], k0, k1);
                mma_f16(s[2 * p],     ql[ks], k0, k1);
                mma_f16(s[2 * p + 1], qh[ks], k2, k3);
                mma_f16(s[2 * p + 1], ql[ks], k2, k3);
            }
        }

        if (kt * 64 + 63 > qb * 128 + warp * 16) {
            const int q0 = qb * 128 + warp * 16 + (lane >> 2);
            const int q1 = q0 + 8;
#pragma unroll
            for (int f = 0; f < 8; f++) {
                const int kc = kt * 64 + f * 8 + (lane & 3) * 2;
                if (kc > q0)     s[f].x = NEG;
                if (kc + 1 > q0) s[f].y = NEG;
                if (kc > q1)     s[f].z = NEG;
                if (kc + 1 > q1) s[f].w = NEG;
            }
        }

        // ---- online softmax (exp2 domain, MUFU exp2f) ----
        float rmax0 = NEG, rmax1 = NEG;
#pragma unroll
        for (int f = 0; f < 8; f++) {
            rmax0 = fmaxf(rmax0, fmaxf(s[f].x, s[f].y));
            rmax1 = fmaxf(rmax1, fmaxf(s[f].z, s[f].w));
        }
        rmax0 = fmaxf(rmax0, __shfl_xor_sync(0xffffffffu, rmax0, 1));
        rmax0 = fmaxf(rmax0, __shfl_xor_sync(0xffffffffu, rmax0, 2));
        rmax1 = fmaxf(rmax1, __shfl_xor_sync(0xffffffffu, rmax1, 1));
        rmax1 = fmaxf(rmax1, __shfl_xor_sync(0xffffffffu, rmax1, 2));

        const float mn0 = fmaxf(m0, rmax0);
        const float mn1 = fmaxf(m1, rmax1);
        const float c0 = exp2f(m0 - mn0);
        const float c1 = exp2f(m1 - mn1);

        float rs0 = 0.f, rs1 = 0.f;
#pragma unroll
        for (int f = 0; f < 8; f++) {
            s[f].x = exp2f(s[f].x - mn0);
            s[f].y = exp2f(s[f].y - mn0);
            s[f].z = exp2f(s[f].z - mn1);
            s[f].w = exp2f(s[f].w - mn1);
            rs0 += s[f].x + s[f].y;
            rs1 += s[f].z + s[f].w;
        }
        rs0 += __shfl_xor_sync(0xffffffffu, rs0, 1);
        rs0 += __shfl_xor_sync(0xffffffffu, rs0, 2);
        rs1 += __shfl_xor_sync(0xffffffffu, rs1, 1);
        rs1 += __shfl_xor_sync(0xffffffffu, rs1, 2);

        l0s = l0s * c0 + rs0;
        l1s = l1s * c1 + rs1;
        m0 = mn0; m1 = mn1;
#pragma unroll
        for (int f = 0; f < 8; f++) {
            o[f].x *= c0; o[f].y *= c0; o[f].z *= c1; o[f].w *= c1;
        }

        // ---- O += P V ----
#pragma unroll
        for (int ks = 0; ks < 4; ks++) {
            uint32_t ap[4];
            ap[0] = pack_h2(s[2 * ks].x,     s[2 * ks].y);
            ap[1] = pack_h2(s[2 * ks].z,     s[2 * ks].w);
            ap[2] = pack_h2(s[2 * ks + 1].x, s[2 * ks + 1].y);
            ap[3] = pack_h2(s[2 * ks + 1].z, s[2 * ks + 1].w);

            const uint32_t vrow = (ks * 16 + (lane & 7) + ((lane >> 3) & 1) * 8) * GSTB;
#pragma unroll
            for (int g = 0; g < 4; g++) {
                const uint32_t vcol = (g * 16 + (lane >> 4) * 8) * 2;
                uint32_t v0, v1, v2, v3;
                LDSM_X4_T(v0, v1, v2, v3, kvb + OFF_VHI + vrow + vcol);
                mma_f16(o[2 * g],     ap, v0, v1);
                mma_f16(o[2 * g + 1], ap, v2, v3);
            }
        }

        // ---- refill buffer (kt+2)%3 with tile kt+2 ----
        if (kt + 2 < nkt) {
            const uint32_t bufb = sb + ((kt + 2) % 3) * KVBUF;
            const int idx = t;
            const int r = idx >> 2;
            const int c8 = (idx & 3) * 16;
            const size_t g = hbase + (size_t)((kt + 2) * 64 + r) * HS + c8;
            const uint32_t so = r * GSTB + c8 * 2;
            cp16(bufb + OFF_KHI + so,      g_khi + g);
            cp16(bufb + OFF_KHI + so + 16, g_khi + g + 8);
            cp16(bufb + OFF_VHI + so,      g_vhi + g);
            cp16(bufb + OFF_VHI + so + 16, g_vhi + g + 8);
        }
        cp_commit();
    }

    // ---- normalize + write split bf16 hi/lo (feeds O projection) ----
    const float inv0 = 1.f / l0s;
    const float inv1 = 1.f / l1s;
    const int r0 = qb * 128 + warp * 16 + (lane >> 2);
    const int r1 = r0 + 8;
#pragma unroll
    for (int f = 0; f < 8; f++) {
        const int col = h * HS + f * 8 + (lane & 3) * 2;
        unsigned l0p, l1p;
        unsigned h0p = pack_hi2(o[f].x * inv0, o[f].y * inv0, l0p);
        unsigned h1p = pack_hi2(o[f].z * inv1, o[f].w * inv1, l1p);
        *(uint32_t*)(g_xhi + (size_t)r0 * DM + col) = h0p;
        *(uint32_t*)(g_xlo + (size_t)r0 * DM + col) = l0p;
        *(uint32_t*)(g_xhi + (size_t)r1 * DM + col) = h1p;
        *(uint32_t*)(g_xlo + (size_t)r1 * DM + col) = l1p;
    }
}

// ============================================================================
// launch
// ============================================================================
extern "C" void kernel_launch(void* const* d_in, const int* in_sizes, int n_in,
                              void* d_out, int out_size)
{
    (void)in_sizes; (void)n_in; (void)out_size;
    const float* x  = (const float*)d_in[0];
    const float* wq = (const float*)d_in[1];
    const float* bq = (const float*)d_in[2];
    const float* wk = (const float*)d_in[3];
    const float* bk = (const float*)d_in[4];
    const float* wv = (const float*)d_in[5];
    const float* bv = (const float*)d_in[6];
    const float* wo = (const float*)d_in[7];
    const float* bo = (const float*)d_in[8];
    float* out = (float*)d_out;

    __nv_bfloat16 *xhi, *xlo;
    cudaGetSymbolAddress((void**)&xhi, g_xhi);
    cudaGetSymbolAddress((void**)&xlo, g_xlo);

    const int GEMM_SMEM = 3 * G_STG;
    cudaFuncSetAttribute(gemm_mma<0>,
                         cudaFuncAttributeMaxDynamicSharedMemorySize, GEMM_SMEM);
    cudaFuncSetAttribute(gemm_mma<1>,
                         cudaFuncAttributeMaxDynamicSharedMemorySize, GEMM_SMEM);
    cudaFuncSetAttribute(attn_mma,
                         cudaFuncAttributeMaxDynamicSharedMemorySize, ATTN_SMEM_TOT);

    split5_kernel<<<dim3(512, 1, 5), 256>>>((const float4*)wq, (const float4*)wk,
                                            (const float4*)wv, (const float4*)wo,
                                            (const float4*)x);

    gemm_mma<0><<<dim3(DM / 128, SQ / 128, 3), 256, GEMM_SMEM>>>(
        xhi, xlo, 0, bq, bk, bv, nullptr);

    attn_mma<<<dim3(SQ / 128, NH), 256, ATTN_SMEM_TOT>>>();

    gemm_mma<1><<<dim3(DM / 128, SQ / 128, 1), 256, GEMM_SMEM>>>(
        xhi, xlo, 3, bo, bo, bo, out);
}

// round 12
// speedup vs baseline: 1.4020x; 1.1724x over previous
#include <cuda_runtime.h>
#include <cuda_bf16.h>
#include <cuda_fp16.h>
#include <cstdint>

#define SQ 4096
#define DM 1024
#define NH 16
#define HS 64
#define QSCALE 0.125f
#define LOG2E 1.4426950408889634f
#define NEG -1e9f

// -------- scratch (no allocations allowed) --------
__device__ __align__(16) __half g_xhi[SQ * DM];        // activations fp16 hi
__device__ __align__(16) __half g_xlo[SQ * DM];        // activations fp16 lo
__device__ __align__(16) __half g_w16[4 * DM * DM];    // weights fp16 single
__device__ __align__(16) __half g_qhi[NH * SQ * HS];   // q fp16 hi (exp2-scaled)
__device__ __align__(16) __half g_qlo[NH * SQ * HS];   // q fp16 lo
__device__ __align__(16) __half g_khi[NH * SQ * HS];   // k fp16
__device__ __align__(16) __half g_vhi[NH * SQ * HS];   // v fp16

// ============================================================================
// helpers
// ============================================================================
__device__ __forceinline__ uint32_t smem_u32(const void* p) {
    uint32_t a;
    asm("{ .reg .u64 t; cvta.to.shared.u64 t, %1; cvt.u32.u64 %0, t; }" : "=r"(a) : "l"(p));
    return a;
}

#define LDSM_X4(r0, r1, r2, r3, addr) \
    asm volatile("ldmatrix.sync.aligned.m8n8.x4.shared.b16 {%0,%1,%2,%3}, [%4];" \
                 : "=r"(r0), "=r"(r1), "=r"(r2), "=r"(r3) : "r"(addr))

#define LDSM_X4_T(r0, r1, r2, r3, addr) \
    asm volatile("ldmatrix.sync.aligned.m8n8.x4.trans.shared.b16 {%0,%1,%2,%3}, [%4];" \
                 : "=r"(r0), "=r"(r1), "=r"(r2), "=r"(r3) : "r"(addr))

__device__ __forceinline__ void mma_f16(float4& d, const uint32_t* a, uint32_t b0, uint32_t b1) {
    asm volatile("mma.sync.aligned.m16n8k16.row.col.f32.f16.f16.f32 "
                 "{%0,%1,%2,%3}, {%4,%5,%6,%7}, {%8,%9}, {%0,%1,%2,%3};"
                 : "+f"(d.x), "+f"(d.y), "+f"(d.z), "+f"(d.w)
                 : "r"(a[0]), "r"(a[1]), "r"(a[2]), "r"(a[3]), "r"(b0), "r"(b1));
}

__device__ __forceinline__ void cp16(uint32_t s, const void* g) {
    asm volatile("cp.async.cg.shared.global [%0], [%1], 16;" :: "r"(s), "l"(g));
}
__device__ __forceinline__ void cp_commit() {
    asm volatile("cp.async.commit_group;" ::: "memory");
}
template <int N>
__device__ __forceinline__ void cp_wait() {
    asm volatile("cp.async.wait_group %0;" :: "n"(N) : "memory");
}

__device__ __forceinline__ unsigned pack_h2(float a, float b) {
    __half2 h = __floats2half2_rn(a, b);
    return *(unsigned*)&h;
}
__device__ __forceinline__ unsigned pack_h2_hi(float a, float b, unsigned& lo) {
    __half ha = __float2half_rn(a);
    __half hb = __float2half_rn(b);
    float ra = a - __half2float(ha);
    float rb = b - __half2float(hb);
    lo = pack_h2(ra, rb);
    __half2 h2v = __halves2half2(ha, hb);
    return *(unsigned*)&h2v;
}

// ============================================================================
// fused split: z<4 -> weights fp16 single, z==4 -> x fp16 hi/lo
// ============================================================================
__global__ __launch_bounds__(256)
void split5_kernel(const float4* __restrict__ w0, const float4* __restrict__ w1,
                   const float4* __restrict__ w2, const float4* __restrict__ w3,
                   const float4* __restrict__ x)
{
    const int z = blockIdx.z;
    if (z < 4) {
        const float4* src = (z == 0) ? w0 : (z == 1) ? w1 : (z == 2) ? w2 : w3;
        uint2* dst = (uint2*)(g_w16 + (size_t)z * DM * DM);
        const int n4 = DM * DM / 4;
        for (int i = blockIdx.x * blockDim.x + threadIdx.x; i < n4;
             i += gridDim.x * blockDim.x) {
            float4 v = src[i];
            dst[i] = make_uint2(pack_h2(v.x, v.y), pack_h2(v.z, v.w));
        }
    } else {
        uint2* hi = (uint2*)g_xhi;
        uint2* lo = (uint2*)g_xlo;
        const int n4 = SQ * DM / 4;
        for (int i = blockIdx.x * blockDim.x + threadIdx.x; i < n4;
             i += gridDim.x * blockDim.x) {
            float4 v = x[i];
            unsigned l0, l1;
            unsigned h0 = pack_h2_hi(v.x, v.y, l0);
            unsigned h1 = pack_h2_hi(v.z, v.w, l1);
            hi[i] = make_uint2(h0, h1);
            lo[i] = make_uint2(l0, l1);
        }
    }
}

// ============================================================================
// GEMM via mma.sync: out = A @ W^T + bias.  A fp16 hi/lo (2 terms), W fp16.
// 128x128 tile, K-chunk 32, ring-3 cp.async, XOR swizzle, ONE sync per chunk.
// MODE 0: QKV epilogue (q fp16 hi/lo scaled, k/v fp16)
// MODE 1: O epilogue (fp32 + bias)
// ============================================================================
#define G_STG 24576            // 3 arrays * 128 rows * 64 B
#define GA_HI 0
#define GA_LO 8192
#define GB_16 16384

__device__ __forceinline__ uint32_t gswz(int row, int chunk) {
    return (uint32_t)(row * 64 + ((chunk ^ ((row >> 1) & 3)) << 4));
}

template <int MODE>
__global__ __launch_bounds__(256, 2)
void gemm_mma(const __half* __restrict__ Ahi,
              const __half* __restrict__ Alo,
              int wslot,
              const float* __restrict__ b0p, const float* __restrict__ b1p,
              const float* __restrict__ b2p,
              float* __restrict__ out)
{
    extern __shared__ __align__(16) char smem[];
    const uint32_t sb = smem_u32(smem);

    const int t = threadIdx.x;
    const int warp = t >> 5, lane = t & 31;
    const int warpM = warp >> 2, warpN = warp & 3;
    const int z = blockIdx.z;
    const int blockM = blockIdx.y * 128;
    const int blockN = blockIdx.x * 128;

    const __half* W = g_w16 + (size_t)(wslot + z) * DM * DM;
    const float* bias = (z == 0) ? b0p : ((z == 1) ? b1p : b2p);

    const int lr = t >> 2;
    const int lch = t & 3;

    float4 acc[4][4];
#pragma unroll
    for (int i = 0; i < 4; i++)
#pragma unroll
        for (int j = 0; j < 4; j++) acc[i][j] = make_float4(0.f, 0.f, 0.f, 0.f);

#pragma unroll
    for (int pc = 0; pc < 2; pc++) {
        const uint32_t stg = sb + pc * G_STG;
        const int kc = pc * 32 + lch * 8;
#pragma unroll
        for (int it = 0; it < 2; it++) {
            const int r = lr + it * 64;
            const uint32_t so = gswz(r, lch);
            cp16(stg + GA_HI + so, Ahi + (size_t)(blockM + r) * DM + kc);
            cp16(stg + GA_LO + so, Alo + (size_t)(blockM + r) * DM + kc);
            cp16(stg + GB_16 + so, W + (size_t)(blockN + r) * DM + kc);
        }
        cp_commit();
    }

    for (int c = 0; c < 32; c++) {
        cp_wait<1>();
        __syncthreads();

        const uint32_t stg = sb + (c % 3) * G_STG;
#pragma unroll
        for (int ks = 0; ks < 2; ks++) {
            const int chA = 2 * ks + (lane >> 4);
            const int chB = 2 * ks + ((lane >> 3) & 1);

            uint32_t a[4][4];
#pragma unroll
            for (int i = 0; i < 4; i++) {
                const int arow = warpM * 64 + i * 16 + (lane & 15);
                LDSM_X4(a[i][0], a[i][1], a[i][2], a[i][3],
                        stg + GA_HI + gswz(arow, chA));
            }
            uint32_t bw[4][2];
#pragma unroll
            for (int p = 0; p < 2; p++) {
                const int brow = warpN * 32 + p * 16 + ((lane >> 4) * 8) + (lane & 7);
                uint32_t m0, m1, m2, m3;
                LDSM_X4(m0, m1, m2, m3, stg + GB_16 + gswz(brow, chB));
                bw[2 * p][0] = m0; bw[2 * p][1] = m1;
                bw[2 * p + 1][0] = m2; bw[2 * p + 1][1] = m3;
            }
#pragma unroll
            for (int i = 0; i < 4; i++)
#pragma unroll
                for (int j = 0; j < 4; j++)
                    mma_f16(acc[i][j], a[i], bw[j][0], bw[j][1]);
#pragma unroll
            for (int i = 0; i < 4; i++) {
                const int arow = warpM * 64 + i * 16 + (lane & 15);
                LDSM_X4(a[i][0], a[i][1], a[i][2], a[i][3],
                        stg + GA_LO + gswz(arow, chA));
            }
#pragma unroll
            for (int i = 0; i < 4; i++)
#pragma unroll
                for (int j = 0; j < 4; j++)
                    mma_f16(acc[i][j], a[i], bw[j][0], bw[j][1]);
        }

        if (c + 2 < 32) {
            const uint32_t stg2 = sb + ((c + 2) % 3) * G_STG;
            const int kc = (c + 2) * 32 + lch * 8;
#pragma unroll
            for (int it = 0; it < 2; it++) {
                const int r = lr + it * 64;
                const uint32_t so = gswz(r, lch);
                cp16(stg2 + GA_HI + so, Ahi + (size_t)(blockM + r) * DM + kc);
                cp16(stg2 + GA_LO + so, Alo + (size_t)(blockM + r) * DM + kc);
                cp16(stg2 + GB_16 + so, W + (size_t)(blockN + r) * DM + kc);
            }
        }
        cp_commit();
    }

    // epilogue
    const float sc = (MODE == 0 && z == 0) ? (QSCALE * LOG2E) : 1.f;
#pragma unroll
    for (int i = 0; i < 4; i++) {
#pragma unroll
        for (int j = 0; j < 4; j++) {
            const int row0 = blockM + warpM * 64 + i * 16 + (lane >> 2);
            const int row1 = row0 + 8;
            const int col = blockN + warpN * 32 + j * 8 + (lane & 3) * 2;
            const float bx = bias[col], by = bias[col + 1];
            const float vx = (acc[i][j].x + bx) * sc;
            const float vy = (acc[i][j].y + by) * sc;
            const float vz = (acc[i][j].z + bx) * sc;
            const float vw = (acc[i][j].w + by) * sc;
            if (MODE == 1) {
                *(float2*)(out + (size_t)row0 * DM + col) = make_float2(vx, vy);
                *(float2*)(out + (size_t)row1 * DM + col) = make_float2(vz, vw);
            } else {
                const int hh = col >> 6, d = col & 63;
                const size_t a0 = (size_t)hh * SQ * HS + (size_t)row0 * HS + d;
                const size_t a1 = (size_t)hh * SQ * HS + (size_t)row1 * HS + d;
                if (z == 0) {
                    unsigned l0, l1;
                    unsigned h0 = pack_h2_hi(vx, vy, l0);
                    unsigned h1 = pack_h2_hi(vz, vw, l1);
                    *(uint32_t*)(g_qhi + a0) = h0;
                    *(uint32_t*)(g_qlo + a0) = l0;
                    *(uint32_t*)(g_qhi + a1) = h1;
                    *(uint32_t*)(g_qlo + a1) = l1;
                } else if (z == 1) {
                    *(uint32_t*)(g_khi + a0) = pack_h2(vx, vy);
                    *(uint32_t*)(g_khi + a1) = pack_h2(vz, vw);
                } else {
                    *(uint32_t*)(g_vhi + a0) = pack_h2(vx, vy);
                    *(uint32_t*)(g_vhi + a1) = pack_h2(vz, vw);
                }
            }
        }
    }
}

// ============================================================================
// Flash attention (unchanged from round 11 winner, epilogue -> fp16 hi/lo).
// ============================================================================
#define GSTB 144
#define KVBUF 18432
#define OFF_KHI 0
#define OFF_VHI 9216
#define ATTN_SMEM_TOT (3 * KVBUF)   // 55296

__global__ __launch_bounds__(256, 2)
void attn_mma()
{
    extern __shared__ __align__(16) char smem[];
    const uint32_t sb = smem_u32(smem);

    const int h  = blockIdx.y;
    const int qb = gridDim.x - 1 - blockIdx.x;
    const int t = threadIdx.x;
    const int warp = t >> 5, lane = t & 31;

    const size_t hbase = (size_t)h * SQ * HS;

#pragma unroll
    for (int it = 0; it < 4; it++) {
        const int idx = it * 256 + t;
        const int r = idx >> 3;
        const int c8 = (idx & 7) * 8;
        const size_t g = hbase + (size_t)(qb * 128 + r) * HS + c8;
        const uint32_t so = r * GSTB + c8 * 2;
        *(uint4*)(smem + so) = *(const uint4*)(g_qhi + g);
        *(uint4*)(smem + 18432 + so) = *(const uint4*)(g_qlo + g);
    }
    __syncthreads();

    uint32_t qh[4][4], ql[4][4];
#pragma unroll
    for (int ks = 0; ks < 4; ks++) {
        const uint32_t ro = (warp * 16 + (lane & 15)) * GSTB + (ks * 16 + (lane >> 4) * 8) * 2;
        LDSM_X4(qh[ks][0], qh[ks][1], qh[ks][2], qh[ks][3], sb + ro);
        LDSM_X4(ql[ks][0], ql[ks][1], ql[ks][2], ql[ks][3], sb + 18432 + ro);
    }
    __syncthreads();

    const int nkt = 2 * qb + 2;

#pragma unroll
    for (int i = 0; i < 2; i++) {
        const uint32_t bufb = sb + i * KVBUF;
        {
            const int idx = t;
            const int r = idx >> 2;
            const int c8 = (idx & 3) * 16;
            const size_t g = hbase + (size_t)(i * 64 + r) * HS + c8;
            const uint32_t so = r * GSTB + c8 * 2;
            cp16(bufb + OFF_KHI + so,      g_khi + g);
            cp16(bufb + OFF_KHI + so + 16, g_khi + g + 8);
            cp16(bufb + OFF_VHI + so,      g_vhi + g);
            cp16(bufb + OFF_VHI + so + 16, g_vhi + g + 8);
        }
        cp_commit();
    }

    float4 o[8];
#pragma unroll
    for (int f = 0; f < 8; f++) o[f] = make_float4(0.f, 0.f, 0.f, 0.f);
    float m0 = -1e30f, m1 = -1e30f, l0s = 0.f, l1s = 0.f;

    for (int kt = 0; kt < nkt; kt++) {
        cp_wait<1>();
        __syncthreads();

        const uint32_t kvb = sb + (kt % 3) * KVBUF;

        float4 s[8];
#pragma unroll
        for (int f = 0; f < 8; f++) s[f] = make_float4(0.f, 0.f, 0.f, 0.f);

#pragma unroll
        for (int ks = 0; ks < 4; ks++) {
            const uint32_t bcol = (ks * 16 + ((lane >> 3) & 1) * 8) * 2;
#pragma unroll
            for (int p = 0; p < 4; p++) {
                const uint32_t brow = (p * 16 + ((lane >> 4) * 8) + (lane & 7)) * GSTB;
                uint32_t k0, k1, k2, k3;
                LDSM_X4(k0, k1, k2, k3, kvb + OFF_KHI + brow + bcol);
                mma_f16(s[2 * p],     qh[ks], k0, k1);
                mma_f16(s[2 * p],     ql[ks], k0, k1);
                mma_f16(s[2 * p + 1], qh[ks], k2, k3);
                mma_f16(s[2 * p + 1], ql[ks], k2, k3);
            }
        }

        if (kt * 64 + 63 > qb * 128 + warp * 16) {
            const int q0 = qb * 128 + warp * 16 + (lane >> 2);
            const int q1 = q0 + 8;
#pragma unroll
            for (int f = 0; f < 8; f++) {
                const int kc = kt * 64 + f * 8 + (lane & 3) * 2;
                if (kc > q0)     s[f].x = NEG;
                if (kc + 1 > q0) s[f].y = NEG;
                if (kc > q1)     s[f].z = NEG;
                if (kc + 1 > q1) s[f].w = NEG;
            }
        }

        float rmax0 = NEG, rmax1 = NEG;
#pragma unroll
        for (int f = 0; f < 8; f++) {
            rmax0 = fmaxf(rmax0, fmaxf(s[f].x, s[f].y));
            rmax1 = fmaxf(rmax1, fmaxf(s[f].z, s[f].w));
        }
        rmax0 = fmaxf(rmax0, __shfl_xor_sync(0xffffffffu, rmax0, 1));
        rmax0 = fmaxf(rmax0, __shfl_xor_sync(0xffffffffu, rmax0, 2));
        rmax1 = fmaxf(rmax1, __shfl_xor_sync(0xffffffffu, rmax1, 1));
        rmax1 = fmaxf(rmax1, __shfl_xor_sync(0xffffffffu, rmax1, 2));

        const float mn0 = fmaxf(m0, rmax0);
        const float mn1 = fmaxf(m1, rmax1);
        const float c0 = exp2f(m0 - mn0);
        const float c1 = exp2f(m1 - mn1);

        float rs0 = 0.f, rs1 = 0.f;
#pragma unroll
        for (int f = 0; f < 8; f++) {
            s[f].x = exp2f(s[f].x - mn0);
            s[f].y = exp2f(s[f].y - mn0);
            s[f].z = exp2f(s[f].z - mn1);
            s[f].w = exp2f(s[f].w - mn1);
            rs0 += s[f].x + s[f].y;
            rs1 += s[f].z + s[f].w;
        }
        rs0 += __shfl_xor_sync(0xffffffffu, rs0, 1);
        rs0 += __shfl_xor_sync(0xffffffffu, rs0, 2);
        rs1 += __shfl_xor_sync(0xffffffffu, rs1, 1);
        rs1 += __shfl_xor_sync(0xffffffffu, rs1, 2);

        l0s = l0s * c0 + rs0;
        l1s = l1s * c1 + rs1;
        m0 = mn0; m1 = mn1;
#pragma unroll
        for (int f = 0; f < 8; f++) {
            o[f].x *= c0; o[f].y *= c0; o[f].z *= c1; o[f].w *= c1;
        }

#pragma unroll
        for (int ks = 0; ks < 4; ks++) {
            uint32_t ap[4];
            ap[0] = pack_h2(s[2 * ks].x,     s[2 * ks].y);
            ap[1] = pack_h2(s[2 * ks].z,     s[2 * ks].w);
            ap[2] = pack_h2(s[2 * ks + 1].x, s[2 * ks + 1].y);
            ap[3] = pack_h2(s[2 * ks + 1].z, s[2 * ks + 1].w);

            const uint32_t vrow = (ks * 16 + (lane & 7) + ((lane >> 3) & 1) * 8) * GSTB;
#pragma unroll
            for (int g = 0; g < 4; g++) {
                const uint32_t vcol = (g * 16 + (lane >> 4) * 8) * 2;
                uint32_t v0, v1, v2, v3;
                LDSM_X4_T(v0, v1, v2, v3, kvb + OFF_VHI + vrow + vcol);
                mma_f16(o[2 * g],     ap, v0, v1);
                mma_f16(o[2 * g + 1], ap, v2, v3);
            }
        }

        if (kt + 2 < nkt) {
            const uint32_t bufb = sb + ((kt + 2) % 3) * KVBUF;
            const int idx = t;
            const int r = idx >> 2;
            const int c8 = (idx & 3) * 16;
            const size_t g = hbase + (size_t)((kt + 2) * 64 + r) * HS + c8;
            const uint32_t so = r * GSTB + c8 * 2;
            cp16(bufb + OFF_KHI + so,      g_khi + g);
            cp16(bufb + OFF_KHI + so + 16, g_khi + g + 8);
            cp16(bufb + OFF_VHI + so,      g_vhi + g);
            cp16(bufb + OFF_VHI + so + 16, g_vhi + g + 8);
        }
        cp_commit();
    }

    // ---- normalize + write fp16 hi/lo (feeds O projection) ----
    const float inv0 = 1.f / l0s;
    const float inv1 = 1.f / l1s;
    const int r0 = qb * 128 + warp * 16 + (lane >> 2);
    const int r1 = r0 + 8;
#pragma unroll
    for (int f = 0; f < 8; f++) {
        const int col = h * HS + f * 8 + (lane & 3) * 2;
        unsigned l0p, l1p;
        unsigned h0p = pack_h2_hi(o[f].x * inv0, o[f].y * inv0, l0p);
        unsigned h1p = pack_h2_hi(o[f].z * inv1, o[f].w * inv1, l1p);
        *(uint32_t*)(g_xhi + (size_t)r0 * DM + col) = h0p;
        *(uint32_t*)(g_xlo + (size_t)r0 * DM + col) = l0p;
        *(uint32_t*)(g_xhi + (size_t)r1 * DM + col) = h1p;
        *(uint32_t*)(g_xlo + (size_t)r1 * DM + col) = l1p;
    }
}

// ============================================================================
// launch
// ============================================================================
extern "C" void kernel_launch(void* const* d_in, const int* in_sizes, int n_in,
                              void* d_out, int out_size)
{
    (void)in_sizes; (void)n_in; (void)out_size;
    const float* x  = (const float*)d_in[0];
    const float* wq = (const float*)d_in[1];
    const float* bq = (const float*)d_in[2];
    const float* wk = (const float*)d_in[3];
    const float* bk = (const float*)d_in[4];
    const float* wv = (const float*)d_in[5];
    const float* bv = (const float*)d_in[6];
    const float* wo = (const float*)d_in[7];
    const float* bo = (const float*)d_in[8];
    float* out = (float*)d_out;

    __half *xhi, *xlo;
    cudaGetSymbolAddress((void**)&xhi, g_xhi);
    cudaGetSymbolAddress((void**)&xlo, g_xlo);

    const int GEMM_SMEM = 3 * G_STG;   // 73728
    cudaFuncSetAttribute(gemm_mma<0>,
                         cudaFuncAttributeMaxDynamicSharedMemorySize, GEMM_SMEM);
    cudaFuncSetAttribute(gemm_mma<1>,
                         cudaFuncAttributeMaxDynamicSharedMemorySize, GEMM_SMEM);
    cudaFuncSetAttribute(attn_mma,
                         cudaFuncAttributeMaxDynamicSharedMemorySize, ATTN_SMEM_TOT);

    split5_kernel<<<dim3(512, 1, 5), 256>>>((const float4*)wq, (const float4*)wk,
                                            (const float4*)wv, (const float4*)wo,
                                            (const float4*)x);

    gemm_mma<0><<<dim3(DM / 128, SQ / 128, 3), 256, GEMM_SMEM>>>(
        xhi, xlo, 0, bq, bk, bv, nullptr);

    attn_mma<<<dim3(SQ / 128, NH), 256, ATTN_SMEM_TOT>>>();

    gemm_mma<1><<<dim3(DM / 128, SQ / 128, 1), 256, GEMM_SMEM>>>(
        xhi, xlo, 3, bo, bo, bo, out);
}

// round 13
// speedup vs baseline: 1.5960x; 1.1384x over previous
#include <cuda_runtime.h>
#include <cuda_bf16.h>
#include <cuda_fp16.h>
#include <cstdint>

#define SQ 4096
#define DM 1024
#define NH 16
#define HS 64
#define QSCALE 0.125f
#define LOG2E 1.4426950408889634f
#define NEG -1e9f

// -------- scratch (no allocations allowed) --------
__device__ __align__(16) __half g_x16[SQ * DM];        // activations fp16 (x, then attn-out)
__device__ __align__(16) __half g_w16[4 * DM * DM];    // weights fp16
__device__ __align__(16) __half g_q16[NH * SQ * HS];   // q fp16 (exp2-domain scaled)
__device__ __align__(16) __half g_k16[NH * SQ * HS];   // k fp16
__device__ __align__(16) __half g_v16[NH * SQ * HS];   // v fp16

// ============================================================================
// helpers
// ============================================================================
__device__ __forceinline__ uint32_t smem_u32(const void* p) {
    uint32_t a;
    asm("{ .reg .u64 t; cvta.to.shared.u64 t, %1; cvt.u32.u64 %0, t; }" : "=r"(a) : "l"(p));
    return a;
}

#define LDSM_X4(r0, r1, r2, r3, addr) \
    asm volatile("ldmatrix.sync.aligned.m8n8.x4.shared.b16 {%0,%1,%2,%3}, [%4];" \
                 : "=r"(r0), "=r"(r1), "=r"(r2), "=r"(r3) : "r"(addr))

#define LDSM_X4_T(r0, r1, r2, r3, addr) \
    asm volatile("ldmatrix.sync.aligned.m8n8.x4.trans.shared.b16 {%0,%1,%2,%3}, [%4];" \
                 : "=r"(r0), "=r"(r1), "=r"(r2), "=r"(r3) : "r"(addr))

__device__ __forceinline__ void mma_f16(float4& d, const uint32_t* a, uint32_t b0, uint32_t b1) {
    asm volatile("mma.sync.aligned.m16n8k16.row.col.f32.f16.f16.f32 "
                 "{%0,%1,%2,%3}, {%4,%5,%6,%7}, {%8,%9}, {%0,%1,%2,%3};"
                 : "+f"(d.x), "+f"(d.y), "+f"(d.z), "+f"(d.w)
                 : "r"(a[0]), "r"(a[1]), "r"(a[2]), "r"(a[3]), "r"(b0), "r"(b1));
}

__device__ __forceinline__ void cp16(uint32_t s, const void* g) {
    asm volatile("cp.async.cg.shared.global [%0], [%1], 16;" :: "r"(s), "l"(g));
}
__device__ __forceinline__ void cp_commit() {
    asm volatile("cp.async.commit_group;" ::: "memory");
}
template <int N>
__device__ __forceinline__ void cp_wait() {
    asm volatile("cp.async.wait_group %0;" :: "n"(N) : "memory");
}

__device__ __forceinline__ unsigned pack_h2(float a, float b) {
    __half2 h = __floats2half2_rn(a, b);
    return *(unsigned*)&h;
}

// ============================================================================
// fused split: z<4 -> weights fp16, z==4 -> x fp16
// ============================================================================
__global__ __launch_bounds__(256)
void split5_kernel(const float4* __restrict__ w0, const float4* __restrict__ w1,
                   const float4* __restrict__ w2, const float4* __restrict__ w3,
                   const float4* __restrict__ x)
{
    const int z = blockIdx.z;
    const float4* src;
    uint2* dst;
    int n4;
    if (z < 4) {
        src = (z == 0) ? w0 : (z == 1) ? w1 : (z == 2) ? w2 : w3;
        dst = (uint2*)(g_w16 + (size_t)z * DM * DM);
        n4 = DM * DM / 4;
    } else {
        src = x;
        dst = (uint2*)g_x16;
        n4 = SQ * DM / 4;
    }
    for (int i = blockIdx.x * blockDim.x + threadIdx.x; i < n4;
         i += gridDim.x * blockDim.x) {
        float4 v = src[i];
        dst[i] = make_uint2(pack_h2(v.x, v.y), pack_h2(v.z, v.w));
    }
}

// ============================================================================
// GEMM via mma.sync: out = A @ W^T + bias.  A fp16, W fp16 (single-term).
// 128x128 tile, K-chunk 64, ring-3 cp.async, SW128 swizzle, ONE sync/chunk.
// Stage = A[128x64] + B[128x64] fp16 = 32 KB; ring-3 = 96 KB; 2 CTAs/SM.
// MODE 0: QKV epilogue (q fp16 scaled, k/v fp16);  MODE 1: O (fp32 + bias)
// ============================================================================
#define G_STG 32768
#define GA 0
#define GB 16384

__device__ __forceinline__ uint32_t swz128(int row, int ch) {
    return (uint32_t)(row * 128 + ((ch ^ (row & 7)) << 4));
}

template <int MODE>
__global__ __launch_bounds__(256, 2)
void gemm_mma(const __half* __restrict__ A,
              int wslot,
              const float* __restrict__ b0p, const float* __restrict__ b1p,
              const float* __restrict__ b2p,
              float* __restrict__ out)
{
    extern __shared__ __align__(16) char smem[];
    const uint32_t sb = smem_u32(smem);

    const int t = threadIdx.x;
    const int warp = t >> 5, lane = t & 31;
    const int warpM = warp >> 2, warpN = warp & 3;
    const int z = blockIdx.z;
    const int blockM = blockIdx.y * 128;
    const int blockN = blockIdx.x * 128;

    const __half* W = g_w16 + (size_t)(wslot + z) * DM * DM;
    const float* bias = (z == 0) ? b0p : ((z == 1) ? b1p : b2p);

    // loader: thread t -> row (t&127) of array (t>>7): 0 = A, 1 = B; 8 chunks
    const int lrow = t & 127;
    const int larr = t >> 7;
    const __half* lsrc = larr ? (W + (size_t)(blockN + lrow) * DM)
                              : (A + (size_t)(blockM + lrow) * DM);
    const uint32_t lbase = (uint32_t)(larr ? GB : GA);

    float4 acc[4][4];
#pragma unroll
    for (int i = 0; i < 4; i++)
#pragma unroll
        for (int j = 0; j < 4; j++) acc[i][j] = make_float4(0.f, 0.f, 0.f, 0.f);

#pragma unroll
    for (int pc = 0; pc < 2; pc++) {
        const uint32_t stg = sb + pc * G_STG + lbase;
        const int kc = pc * 64;
#pragma unroll
        for (int ch = 0; ch < 8; ch++)
            cp16(stg + swz128(lrow, ch), lsrc + kc + ch * 8);
        cp_commit();
    }

    for (int c = 0; c < 16; c++) {
        cp_wait<1>();
        __syncthreads();

        const uint32_t stg = sb + (c % 3) * G_STG;
#pragma unroll
        for (int ks = 0; ks < 4; ks++) {
            const int chA = 2 * ks + (lane >> 4);
            const int chB = 2 * ks + ((lane >> 3) & 1);

            uint32_t a[4][4];
#pragma unroll
            for (int i = 0; i < 4; i++) {
                const int arow = warpM * 64 + i * 16 + (lane & 15);
                LDSM_X4(a[i][0], a[i][1], a[i][2], a[i][3],
                        stg + GA + swz128(arow, chA));
            }
            uint32_t bw[4][2];
#pragma unroll
            for (int p = 0; p < 2; p++) {
                const int brow = warpN * 32 + p * 16 + ((lane >> 4) * 8) + (lane & 7);
                uint32_t m0, m1, m2, m3;
                LDSM_X4(m0, m1, m2, m3, stg + GB + swz128(brow, chB));
                bw[2 * p][0] = m0; bw[2 * p][1] = m1;
                bw[2 * p + 1][0] = m2; bw[2 * p + 1][1] = m3;
            }
#pragma unroll
            for (int i = 0; i < 4; i++)
#pragma unroll
                for (int j = 0; j < 4; j++)
                    mma_f16(acc[i][j], a[i], bw[j][0], bw[j][1]);
        }

        if (c + 2 < 16) {
            const uint32_t stg2 = sb + ((c + 2) % 3) * G_STG + lbase;
            const int kc = (c + 2) * 64;
#pragma unroll
            for (int ch = 0; ch < 8; ch++)
                cp16(stg2 + swz128(lrow, ch), lsrc + kc + ch * 8);
        }
        cp_commit();
    }

    // epilogue
    const float sc = (MODE == 0 && z == 0) ? (QSCALE * LOG2E) : 1.f;
#pragma unroll
    for (int i = 0; i < 4; i++) {
#pragma unroll
        for (int j = 0; j < 4; j++) {
            const int row0 = blockM + warpM * 64 + i * 16 + (lane >> 2);
            const int row1 = row0 + 8;
            const int col = blockN + warpN * 32 + j * 8 + (lane & 3) * 2;
            const float bx = bias[col], by = bias[col + 1];
            const float vx = (acc[i][j].x + bx) * sc;
            const float vy = (acc[i][j].y + by) * sc;
            const float vz = (acc[i][j].z + bx) * sc;
            const float vw = (acc[i][j].w + by) * sc;
            if (MODE == 1) {
                *(float2*)(out + (size_t)row0 * DM + col) = make_float2(vx, vy);
                *(float2*)(out + (size_t)row1 * DM + col) = make_float2(vz, vw);
            } else {
                const int hh = col >> 6, d = col & 63;
                const size_t a0 = (size_t)hh * SQ * HS + (size_t)row0 * HS + d;
                const size_t a1 = (size_t)hh * SQ * HS + (size_t)row1 * HS + d;
                __half* dst = (z == 0) ? g_q16 : ((z == 1) ? g_k16 : g_v16);
                *(uint32_t*)(dst + a0) = pack_h2(vx, vy);
                *(uint32_t*)(dst + a1) = pack_h2(vz, vw);
            }
        }
    }
}

// ============================================================================
// Flash attention: ring-3 cp.async, ONE sync per k-tile, exp2f softmax.
// S = Q(fp16) x K(fp16); PV = P fp16 x V fp16. Output fp16 -> g_x16.
// ============================================================================
#define GSTB 144
#define KVBUF 18432
#define OFF_K 0
#define OFF_V 9216
#define ATTN_SMEM_TOT (3 * KVBUF)   // 55296

__global__ __launch_bounds__(256, 2)
void attn_mma()
{
    extern __shared__ __align__(16) char smem[];
    const uint32_t sb = smem_u32(smem);

    const int h  = blockIdx.y;
    const int qb = gridDim.x - 1 - blockIdx.x;
    const int t = threadIdx.x;
    const int warp = t >> 5, lane = t & 31;

    const size_t hbase = (size_t)h * SQ * HS;

    // ---- stage Q tile (128 rows, fp16) — region reused by ring after ----
#pragma unroll
    for (int it = 0; it < 2; it++) {
        const int idx = it * 256 + t;
        const int r = idx >> 2;
        const int c8 = (idx & 3) * 16;
        const size_t g = hbase + (size_t)(qb * 128 + r) * HS + c8;
        const uint32_t so = r * GSTB + c8 * 2;
        *(uint4*)(smem + so) = *(const uint4*)(g_q16 + g);
        *(uint4*)(smem + so + 16) = *(const uint4*)(g_q16 + g + 8);
    }
    __syncthreads();

    uint32_t qh[4][4];
#pragma unroll
    for (int ks = 0; ks < 4; ks++) {
        const uint32_t ro = (warp * 16 + (lane & 15)) * GSTB + (ks * 16 + (lane >> 4) * 8) * 2;
        LDSM_X4(qh[ks][0], qh[ks][1], qh[ks][2], qh[ks][3], sb + ro);
    }
    __syncthreads();   // Q consumed before ring reuse

    const int nkt = 2 * qb + 2;

#pragma unroll
    for (int i = 0; i < 2; i++) {
        const uint32_t bufb = sb + i * KVBUF;
        const int r = t >> 2;
        const int c8 = (t & 3) * 16;
        const size_t g = hbase + (size_t)(i * 64 + r) * HS + c8;
        const uint32_t so = r * GSTB + c8 * 2;
        cp16(bufb + OFF_K + so,      g_k16 + g);
        cp16(bufb + OFF_K + so + 16, g_k16 + g + 8);
        cp16(bufb + OFF_V + so,      g_v16 + g);
        cp16(bufb + OFF_V + so + 16, g_v16 + g + 8);
        cp_commit();
    }

    float4 o[8];
#pragma unroll
    for (int f = 0; f < 8; f++) o[f] = make_float4(0.f, 0.f, 0.f, 0.f);
    float m0 = -1e30f, m1 = -1e30f, l0s = 0.f, l1s = 0.f;

    for (int kt = 0; kt < nkt; kt++) {
        cp_wait<1>();
        __syncthreads();

        const uint32_t kvb = sb + (kt % 3) * KVBUF;

        float4 s[8];
#pragma unroll
        for (int f = 0; f < 8; f++) s[f] = make_float4(0.f, 0.f, 0.f, 0.f);

#pragma unroll
        for (int ks = 0; ks < 4; ks++) {
            const uint32_t bcol = (ks * 16 + ((lane >> 3) & 1) * 8) * 2;
#pragma unroll
            for (int p = 0; p < 4; p++) {
                const uint32_t brow = (p * 16 + ((lane >> 4) * 8) + (lane & 7)) * GSTB;
                uint32_t k0, k1, k2, k3;
                LDSM_X4(k0, k1, k2, k3, kvb + OFF_K + brow + bcol);
                mma_f16(s[2 * p],     qh[ks], k0, k1);
                mma_f16(s[2 * p + 1], qh[ks], k2, k3);
            }
        }

        if (kt * 64 + 63 > qb * 128 + warp * 16) {
            const int q0 = qb * 128 + warp * 16 + (lane >> 2);
            const int q1 = q0 + 8;
#pragma unroll
            for (int f = 0; f < 8; f++) {
                const int kc = kt * 64 + f * 8 + (lane & 3) * 2;
                if (kc > q0)     s[f].x = NEG;
                if (kc + 1 > q0) s[f].y = NEG;
                if (kc > q1)     s[f].z = NEG;
                if (kc + 1 > q1) s[f].w = NEG;
            }
        }

        float rmax0 = NEG, rmax1 = NEG;
#pragma unroll
        for (int f = 0; f < 8; f++) {
            rmax0 = fmaxf(rmax0, fmaxf(s[f].x, s[f].y));
            rmax1 = fmaxf(rmax1, fmaxf(s[f].z, s[f].w));
        }
        rmax0 = fmaxf(rmax0, __shfl_xor_sync(0xffffffffu, rmax0, 1));
        rmax0 = fmaxf(rmax0, __shfl_xor_sync(0xffffffffu, rmax0, 2));
        rmax1 = fmaxf(rmax1, __shfl_xor_sync(0xffffffffu, rmax1, 1));
        rmax1 = fmaxf(rmax1, __shfl_xor_sync(0xffffffffu, rmax1, 2));

        const float mn0 = fmaxf(m0, rmax0);
        const float mn1 = fmaxf(m1, rmax1);
        const float c0 = exp2f(m0 - mn0);
        const float c1 = exp2f(m1 - mn1);

        float rs0 = 0.f, rs1 = 0.f;
#pragma unroll
        for (int f = 0; f < 8; f++) {
            s[f].x = exp2f(s[f].x - mn0);
            s[f].y = exp2f(s[f].y - mn0);
            s[f].z = exp2f(s[f].z - mn1);
            s[f].w = exp2f(s[f].w - mn1);
            rs0 += s[f].x + s[f].y;
            rs1 += s[f].z + s[f].w;
        }
        rs0 += __shfl_xor_sync(0xffffffffu, rs0, 1);
        rs0 += __shfl_xor_sync(0xffffffffu, rs0, 2);
        rs1 += __shfl_xor_sync(0xffffffffu, rs1, 1);
        rs1 += __shfl_xor_sync(0xffffffffu, rs1, 2);

        l0s = l0s * c0 + rs0;
        l1s = l1s * c1 + rs1;
        m0 = mn0; m1 = mn1;
#pragma unroll
        for (int f = 0; f < 8; f++) {
            o[f].x *= c0; o[f].y *= c0; o[f].z *= c1; o[f].w *= c1;
        }

#pragma unroll
        for (int ks = 0; ks < 4; ks++) {
            uint32_t ap[4];
            ap[0] = pack_h2(s[2 * ks].x,     s[2 * ks].y);
            ap[1] = pack_h2(s[2 * ks].z,     s[2 * ks].w);
            ap[2] = pack_h2(s[2 * ks + 1].x, s[2 * ks + 1].y);
            ap[3] = pack_h2(s[2 * ks + 1].z, s[2 * ks + 1].w);

            const uint32_t vrow = (ks * 16 + (lane & 7) + ((lane >> 3) & 1) * 8) * GSTB;
#pragma unroll
            for (int g = 0; g < 4; g++) {
                const uint32_t vcol = (g * 16 + (lane >> 4) * 8) * 2;
                uint32_t v0, v1, v2, v3;
                LDSM_X4_T(v0, v1, v2, v3, kvb + OFF_V + vrow + vcol);
                mma_f16(o[2 * g],     ap, v0, v1);
                mma_f16(o[2 * g + 1], ap, v2, v3);
            }
        }

        if (kt + 2 < nkt) {
            const uint32_t bufb = sb + ((kt + 2) % 3) * KVBUF;
            const int r = t >> 2;
            const int c8 = (t & 3) * 16;
            const size_t g = hbase + (size_t)((kt + 2) * 64 + r) * HS + c8;
            const uint32_t so = r * GSTB + c8 * 2;
            cp16(bufb + OFF_K + so,      g_k16 + g);
            cp16(bufb + OFF_K + so + 16, g_k16 + g + 8);
            cp16(bufb + OFF_V + so,      g_v16 + g);
            cp16(bufb + OFF_V + so + 16, g_v16 + g + 8);
        }
        cp_commit();
    }

    // ---- normalize + write fp16 (feeds O projection) ----
    const float inv0 = 1.f / l0s;
    const float inv1 = 1.f / l1s;
    const int r0 = qb * 128 + warp * 16 + (lane >> 2);
    const int r1 = r0 + 8;
#pragma unroll
    for (int f = 0; f < 8; f++) {
        const int col = h * HS + f * 8 + (lane & 3) * 2;
        *(uint32_t*)(g_x16 + (size_t)r0 * DM + col) = pack_h2(o[f].x * inv0, o[f].y * inv0);
        *(uint32_t*)(g_x16 + (size_t)r1 * DM + col) = pack_h2(o[f].z * inv1, o[f].w * inv1);
    }
}

// ============================================================================
// launch
// ============================================================================
extern "C" void kernel_launch(void* const* d_in, const int* in_sizes, int n_in,
                              void* d_out, int out_size)
{
    (void)in_sizes; (void)n_in; (void)out_size;
    const float* x  = (const float*)d_in[0];
    const float* wq = (const float*)d_in[1];
    const float* bq = (const float*)d_in[2];
    const float* wk = (const float*)d_in[3];
    const float* bk = (const float*)d_in[4];
    const float* wv = (const float*)d_in[5];
    const float* bv = (const float*)d_in[6];
    const float* wo = (const float*)d_in[7];
    const float* bo = (const float*)d_in[8];
    float* out = (float*)d_out;

    __half* x16;
    cudaGetSymbolAddress((void**)&x16, g_x16);

    const int GEMM_SMEM = 3 * G_STG;   // 98304
    cudaFuncSetAttribute(gemm_mma<0>,
                         cudaFuncAttributeMaxDynamicSharedMemorySize, GEMM_SMEM);
    cudaFuncSetAttribute(gemm_mma<1>,
                         cudaFuncAttributeMaxDynamicSharedMemorySize, GEMM_SMEM);
    cudaFuncSetAttribute(attn_mma,
                         cudaFuncAttributeMaxDynamicSharedMemorySize, ATTN_SMEM_TOT);

    split5_kernel<<<dim3(512, 1, 5), 256>>>((const float4*)wq, (const float4*)wk,
                                            (const float4*)wv, (const float4*)wo,
                                            (const float4*)x);

    gemm_mma<0><<<dim3(DM / 128, SQ / 128, 3), 256, GEMM_SMEM>>>(
        x16, 0, bq, bk, bv, nullptr);

    attn_mma<<<dim3(SQ / 128, NH), 256, ATTN_SMEM_TOT>>>();

    gemm_mma<1><<<dim3(DM / 128, SQ / 128, 1), 256, GEMM_SMEM>>>(
        x16, 3, bo, bo, bo, out);
}

// round 14
// speedup vs baseline: 1.6446x; 1.0305x over previous
#include <cuda_runtime.h>
#include <cuda_bf16.h>
#include <cuda_fp16.h>
#include <cstdint>

#define SQ 4096
#define DM 1024
#define NH 16
#define HS 64
#define QSCALE 0.125f
#define LOG2E 1.4426950408889634f
#define NEG -1e9f

// -------- scratch (no allocations allowed) --------
__device__ __align__(16) __half g_x16[SQ * DM];        // activations fp16 (x, then attn-out)
__device__ __align__(16) __half g_w16[4 * DM * DM];    // weights fp16
__device__ __align__(16) __half g_q16[NH * SQ * HS];   // q fp16 (exp2-domain scaled)
__device__ __align__(16) __half g_k16[NH * SQ * HS];   // k fp16
__device__ __align__(16) __half g_v16[NH * SQ * HS];   // v fp16

// ============================================================================
// helpers
// ============================================================================
__device__ __forceinline__ uint32_t smem_u32(const void* p) {
    uint32_t a;
    asm("{ .reg .u64 t; cvta.to.shared.u64 t, %1; cvt.u32.u64 %0, t; }" : "=r"(a) : "l"(p));
    return a;
}

#define LDSM_X4(r0, r1, r2, r3, addr) \
    asm volatile("ldmatrix.sync.aligned.m8n8.x4.shared.b16 {%0,%1,%2,%3}, [%4];" \
                 : "=r"(r0), "=r"(r1), "=r"(r2), "=r"(r3) : "r"(addr))

#define LDSM_X4_T(r0, r1, r2, r3, addr) \
    asm volatile("ldmatrix.sync.aligned.m8n8.x4.trans.shared.b16 {%0,%1,%2,%3}, [%4];" \
                 : "=r"(r0), "=r"(r1), "=r"(r2), "=r"(r3) : "r"(addr))

__device__ __forceinline__ void mma_f16(float4& d, const uint32_t* a, uint32_t b0, uint32_t b1) {
    asm volatile("mma.sync.aligned.m16n8k16.row.col.f32.f16.f16.f32 "
                 "{%0,%1,%2,%3}, {%4,%5,%6,%7}, {%8,%9}, {%0,%1,%2,%3};"
                 : "+f"(d.x), "+f"(d.y), "+f"(d.z), "+f"(d.w)
                 : "r"(a[0]), "r"(a[1]), "r"(a[2]), "r"(a[3]), "r"(b0), "r"(b1));
}

__device__ __forceinline__ void cp16(uint32_t s, const void* g) {
    asm volatile("cp.async.cg.shared.global [%0], [%1], 16;" :: "r"(s), "l"(g));
}
__device__ __forceinline__ void cp_commit() {
    asm volatile("cp.async.commit_group;" ::: "memory");
}
template <int N>
__device__ __forceinline__ void cp_wait() {
    asm volatile("cp.async.wait_group %0;" :: "n"(N) : "memory");
}

__device__ __forceinline__ unsigned pack_h2(float a, float b) {
    __half2 h = __floats2half2_rn(a, b);
    return *(unsigned*)&h;
}

// ============================================================================
// fused split: z<4 -> weights fp16, z==4 -> x fp16
// ============================================================================
__global__ __launch_bounds__(256)
void split5_kernel(const float4* __restrict__ w0, const float4* __restrict__ w1,
                   const float4* __restrict__ w2, const float4* __restrict__ w3,
                   const float4* __restrict__ x)
{
    const int z = blockIdx.z;
    const float4* src;
    uint2* dst;
    int n4;
    if (z < 4) {
        src = (z == 0) ? w0 : (z == 1) ? w1 : (z == 2) ? w2 : w3;
        dst = (uint2*)(g_w16 + (size_t)z * DM * DM);
        n4 = DM * DM / 4;
    } else {
        src = x;
        dst = (uint2*)g_x16;
        n4 = SQ * DM / 4;
    }
    for (int i = blockIdx.x * blockDim.x + threadIdx.x; i < n4;
         i += gridDim.x * blockDim.x) {
        float4 v = src[i];
        dst[i] = make_uint2(pack_h2(v.x, v.y), pack_h2(v.z, v.w));
    }
}

// ============================================================================
// GEMM via mma.sync: out = A @ W^T + bias.  A fp16, W fp16.
// 128x128 tile, K-chunk 32, RING-4 cp.async (wait<2>), XOR swizzle,
// ONE sync per chunk. Stage = 16 KB; ring-4 = 64 KB; 2 CTAs/SM.
// MODE 0: QKV epilogue;  MODE 1: O epilogue (fp32 + bias)
// ============================================================================
#define G_STG 16384
#define GA 0
#define GB 8192

__device__ __forceinline__ uint32_t gswz(int row, int ch) {
    return (uint32_t)(row * 64 + ((ch ^ ((row >> 1) & 3)) << 4));
}

template <int MODE>
__global__ __launch_bounds__(256, 2)
void gemm_mma(const __half* __restrict__ A,
              int wslot,
              const float* __restrict__ b0p, const float* __restrict__ b1p,
              const float* __restrict__ b2p,
              float* __restrict__ out)
{
    extern __shared__ __align__(16) char smem[];
    const uint32_t sb = smem_u32(smem);

    const int t = threadIdx.x;
    const int warp = t >> 5, lane = t & 31;
    const int warpM = warp >> 2, warpN = warp & 3;
    const int z = blockIdx.z;
    const int blockM = blockIdx.y * 128;
    const int blockN = blockIdx.x * 128;

    const __half* W = g_w16 + (size_t)(wslot + z) * DM * DM;
    const float* bias = (z == 0) ? b0p : ((z == 1) ? b1p : b2p);

    // loader: thread t -> row (t&127) of array (t>>7): 0 = A, 1 = W; 4 cp16/row
    const int lrow = t & 127;
    const int larr = t >> 7;
    const __half* lsrc = larr ? (W + (size_t)(blockN + lrow) * DM)
                              : (A + (size_t)(blockM + lrow) * DM);
    const uint32_t lbase = (uint32_t)(larr ? GB : GA);

    float4 acc[4][4];
#pragma unroll
    for (int i = 0; i < 4; i++)
#pragma unroll
        for (int j = 0; j < 4; j++) acc[i][j] = make_float4(0.f, 0.f, 0.f, 0.f);

    // prologue: chunks 0,1,2 -> stages 0,1,2 (3 commit groups)
#pragma unroll
    for (int pc = 0; pc < 3; pc++) {
        const uint32_t stg = sb + pc * G_STG + lbase;
        const int kc = pc * 32;
#pragma unroll
        for (int ch = 0; ch < 4; ch++)
            cp16(stg + gswz(lrow, ch), lsrc + kc + ch * 8);
        cp_commit();
    }

    for (int c = 0; c < 32; c++) {
        cp_wait<2>();
        __syncthreads();

        const uint32_t stg = sb + (c & 3) * G_STG;
#pragma unroll
        for (int ks = 0; ks < 2; ks++) {
            const int chA = 2 * ks + (lane >> 4);
            const int chB = 2 * ks + ((lane >> 3) & 1);

            uint32_t a[4][4];
#pragma unroll
            for (int i = 0; i < 4; i++) {
                const int arow = warpM * 64 + i * 16 + (lane & 15);
                LDSM_X4(a[i][0], a[i][1], a[i][2], a[i][3],
                        stg + GA + gswz(arow, chA));
            }
            uint32_t bw[4][2];
#pragma unroll
            for (int p = 0; p < 2; p++) {
                const int brow = warpN * 32 + p * 16 + ((lane >> 4) * 8) + (lane & 7);
                uint32_t m0, m1, m2, m3;
                LDSM_X4(m0, m1, m2, m3, stg + GB + gswz(brow, chB));
                bw[2 * p][0] = m0; bw[2 * p][1] = m1;
                bw[2 * p + 1][0] = m2; bw[2 * p + 1][1] = m3;
            }
#pragma unroll
            for (int i = 0; i < 4; i++)
#pragma unroll
                for (int j = 0; j < 4; j++)
                    mma_f16(acc[i][j], a[i], bw[j][0], bw[j][1]);
        }

        // issue chunk c+3 into stage (c+3)&3 (last read at iter c-1; top sync fences)
        if (c + 3 < 32) {
            const uint32_t stg2 = sb + ((c + 3) & 3) * G_STG + lbase;
            const int kc = (c + 3) * 32;
#pragma unroll
            for (int ch = 0; ch < 4; ch++)
                cp16(stg2 + gswz(lrow, ch), lsrc + kc + ch * 8);
        }
        cp_commit();
    }

    // epilogue
    const float sc = (MODE == 0 && z == 0) ? (QSCALE * LOG2E) : 1.f;
#pragma unroll
    for (int i = 0; i < 4; i++) {
#pragma unroll
        for (int j = 0; j < 4; j++) {
            const int row0 = blockM + warpM * 64 + i * 16 + (lane >> 2);
            const int row1 = row0 + 8;
            const int col = blockN + warpN * 32 + j * 8 + (lane & 3) * 2;
            const float bx = bias[col], by = bias[col + 1];
            const float vx = (acc[i][j].x + bx) * sc;
            const float vy = (acc[i][j].y + by) * sc;
            const float vz = (acc[i][j].z + bx) * sc;
            const float vw = (acc[i][j].w + by) * sc;
            if (MODE == 1) {
                *(float2*)(out + (size_t)row0 * DM + col) = make_float2(vx, vy);
                *(float2*)(out + (size_t)row1 * DM + col) = make_float2(vz, vw);
            } else {
                const int hh = col >> 6, d = col & 63;
                const size_t a0 = (size_t)hh * SQ * HS + (size_t)row0 * HS + d;
                const size_t a1 = (size_t)hh * SQ * HS + (size_t)row1 * HS + d;
                __half* dst = (z == 0) ? g_q16 : ((z == 1) ? g_k16 : g_v16);
                *(uint32_t*)(dst + a0) = pack_h2(vx, vy);
                *(uint32_t*)(dst + a1) = pack_h2(vz, vw);
            }
        }
    }
}

// ============================================================================
// Flash attention: RING-4 cp.async (wait<2>), ONE sync per k-tile, exp2f.
// S = Q(fp16) x K(fp16); PV = P fp16 x V fp16. Output fp16 -> g_x16.
// ============================================================================
#define GSTB 144
#define KVBUF 18432
#define OFF_K 0
#define OFF_V 9216
#define ATTN_SMEM_TOT (4 * KVBUF)   // 73728

__global__ __launch_bounds__(256, 2)
void attn_mma()
{
    extern __shared__ __align__(16) char smem[];
    const uint32_t sb = smem_u32(smem);

    const int h  = blockIdx.y;
    const int qb = gridDim.x - 1 - blockIdx.x;
    const int t = threadIdx.x;
    const int warp = t >> 5, lane = t & 31;

    const size_t hbase = (size_t)h * SQ * HS;

    // ---- stage Q tile (128 rows, fp16) — region reused by ring after ----
#pragma unroll
    for (int it = 0; it < 2; it++) {
        const int idx = it * 256 + t;
        const int r = idx >> 2;
        const int c8 = (idx & 3) * 16;
        const size_t g = hbase + (size_t)(qb * 128 + r) * HS + c8;
        const uint32_t so = r * GSTB + c8 * 2;
        *(uint4*)(smem + so) = *(const uint4*)(g_q16 + g);
        *(uint4*)(smem + so + 16) = *(const uint4*)(g_q16 + g + 8);
    }
    __syncthreads();

    uint32_t qh[4][4];
#pragma unroll
    for (int ks = 0; ks < 4; ks++) {
        const uint32_t ro = (warp * 16 + (lane & 15)) * GSTB + (ks * 16 + (lane >> 4) * 8) * 2;
        LDSM_X4(qh[ks][0], qh[ks][1], qh[ks][2], qh[ks][3], sb + ro);
    }
    __syncthreads();   // Q consumed before ring reuse

    const int nkt = 2 * qb + 2;

    // prologue: tiles 0..2 -> buffers 0..2 (guarded; 3 commits)
#pragma unroll
    for (int i = 0; i < 3; i++) {
        if (i < nkt) {
            const uint32_t bufb = sb + i * KVBUF;
            const int r = t >> 2;
            const int c8 = (t & 3) * 16;
            const size_t g = hbase + (size_t)(i * 64 + r) * HS + c8;
            const uint32_t so = r * GSTB + c8 * 2;
            cp16(bufb + OFF_K + so,      g_k16 + g);
            cp16(bufb + OFF_K + so + 16, g_k16 + g + 8);
            cp16(bufb + OFF_V + so,      g_v16 + g);
            cp16(bufb + OFF_V + so + 16, g_v16 + g + 8);
        }
        cp_commit();
    }

    float4 o[8];
#pragma unroll
    for (int f = 0; f < 8; f++) o[f] = make_float4(0.f, 0.f, 0.f, 0.f);
    float m0 = -1e30f, m1 = -1e30f, l0s = 0.f, l1s = 0.f;

    for (int kt = 0; kt < nkt; kt++) {
        cp_wait<2>();
        __syncthreads();

        const uint32_t kvb = sb + (kt & 3) * KVBUF;

        float4 s[8];
#pragma unroll
        for (int f = 0; f < 8; f++) s[f] = make_float4(0.f, 0.f, 0.f, 0.f);

#pragma unroll
        for (int ks = 0; ks < 4; ks++) {
            const uint32_t bcol = (ks * 16 + ((lane >> 3) & 1) * 8) * 2;
#pragma unroll
            for (int p = 0; p < 4; p++) {
                const uint32_t brow = (p * 16 + ((lane >> 4) * 8) + (lane & 7)) * GSTB;
                uint32_t k0, k1, k2, k3;
                LDSM_X4(k0, k1, k2, k3, kvb + OFF_K + brow + bcol);
                mma_f16(s[2 * p],     qh[ks], k0, k1);
                mma_f16(s[2 * p + 1], qh[ks], k2, k3);
            }
        }

        if (kt * 64 + 63 > qb * 128 + warp * 16) {
            const int q0 = qb * 128 + warp * 16 + (lane >> 2);
            const int q1 = q0 + 8;
#pragma unroll
            for (int f = 0; f < 8; f++) {
                const int kc = kt * 64 + f * 8 + (lane & 3) * 2;
                if (kc > q0)     s[f].x = NEG;
                if (kc + 1 > q0) s[f].y = NEG;
                if (kc > q1)     s[f].z = NEG;
                if (kc + 1 > q1) s[f].w = NEG;
            }
        }

        float rmax0 = NEG, rmax1 = NEG;
#pragma unroll
        for (int f = 0; f < 8; f++) {
            rmax0 = fmaxf(rmax0, fmaxf(s[f].x, s[f].y));
            rmax1 = fmaxf(rmax1, fmaxf(s[f].z, s[f].w));
        }
        rmax0 = fmaxf(rmax0, __shfl_xor_sync(0xffffffffu, rmax0, 1));
        rmax0 = fmaxf(rmax0, __shfl_xor_sync(0xffffffffu, rmax0, 2));
        rmax1 = fmaxf(rmax1, __shfl_xor_sync(0xffffffffu, rmax1, 1));
        rmax1 = fmaxf(rmax1, __shfl_xor_sync(0xffffffffu, rmax1, 2));

        const float mn0 = fmaxf(m0, rmax0);
        const float mn1 = fmaxf(m1, rmax1);
        const float c0 = exp2f(m0 - mn0);
        const float c1 = exp2f(m1 - mn1);

        float rs0 = 0.f, rs1 = 0.f;
#pragma unroll
        for (int f = 0; f < 8; f++) {
            s[f].x = exp2f(s[f].x - mn0);
            s[f].y = exp2f(s[f].y - mn0);
            s[f].z = exp2f(s[f].z - mn1);
            s[f].w = exp2f(s[f].w - mn1);
            rs0 += s[f].x + s[f].y;
            rs1 += s[f].z + s[f].w;
        }
        rs0 += __shfl_xor_sync(0xffffffffu, rs0, 1);
        rs0 += __shfl_xor_sync(0xffffffffu, rs0, 2);
        rs1 += __shfl_xor_sync(0xffffffffu, rs1, 1);
        rs1 += __shfl_xor_sync(0xffffffffu, rs1, 2);

        l0s = l0s * c0 + rs0;
        l1s = l1s * c1 + rs1;
        m0 = mn0; m1 = mn1;
#pragma unroll
        for (int f = 0; f < 8; f++) {
            o[f].x *= c0; o[f].y *= c0; o[f].z *= c1; o[f].w *= c1;
        }

#pragma unroll
        for (int ks = 0; ks < 4; ks++) {
            uint32_t ap[4];
            ap[0] = pack_h2(s[2 * ks].x,     s[2 * ks].y);
            ap[1] = pack_h2(s[2 * ks].z,     s[2 * ks].w);
            ap[2] = pack_h2(s[2 * ks + 1].x, s[2 * ks + 1].y);
            ap[3] = pack_h2(s[2 * ks + 1].z, s[2 * ks + 1].w);

            const uint32_t vrow = (ks * 16 + (lane & 7) + ((lane >> 3) & 1) * 8) * GSTB;
#pragma unroll
            for (int g = 0; g < 4; g++) {
                const uint32_t vcol = (g * 16 + (lane >> 4) * 8) * 2;
                uint32_t v0, v1, v2, v3;
                LDSM_X4_T(v0, v1, v2, v3, kvb + OFF_V + vrow + vcol);
                mma_f16(o[2 * g],     ap, v0, v1);
                mma_f16(o[2 * g + 1], ap, v2, v3);
            }
        }

        // refill buffer (kt+3)&3 with tile kt+3 (last read at kt-1; top sync fences)
        if (kt + 3 < nkt) {
            const uint32_t bufb = sb + ((kt + 3) & 3) * KVBUF;
            const int r = t >> 2;
            const int c8 = (t & 3) * 16;
            const size_t g = hbase + (size_t)((kt + 3) * 64 + r) * HS + c8;
            const uint32_t so = r * GSTB + c8 * 2;
            cp16(bufb + OFF_K + so,      g_k16 + g);
            cp16(bufb + OFF_K + so + 16, g_k16 + g + 8);
            cp16(bufb + OFF_V + so,      g_v16 + g);
            cp16(bufb + OFF_V + so + 16, g_v16 + g + 8);
        }
        cp_commit();
    }

    // ---- normalize + write fp16 (feeds O projection) ----
    const float inv0 = 1.f / l0s;
    const float inv1 = 1.f / l1s;
    const int r0 = qb * 128 + warp * 16 + (lane >> 2);
    const int r1 = r0 + 8;
#pragma unroll
    for (int f = 0; f < 8; f++) {
        const int col = h * HS + f * 8 + (lane & 3) * 2;
        *(uint32_t*)(g_x16 + (size_t)r0 * DM + col) = pack_h2(o[f].x * inv0, o[f].y * inv0);
        *(uint32_t*)(g_x16 + (size_t)r1 * DM + col) = pack_h2(o[f].z * inv1, o[f].w * inv1);
    }
}

// ============================================================================
// launch
// ============================================================================
extern "C" void kernel_launch(void* const* d_in, const int* in_sizes, int n_in,
                              void* d_out, int out_size)
{
    (void)in_sizes; (void)n_in; (void)out_size;
    const float* x  = (const float*)d_in[0];
    const float* wq = (const float*)d_in[1];
    const float* bq = (const float*)d_in[2];
    const float* wk = (const float*)d_in[3];
    const float* bk = (const float*)d_in[4];
    const float* wv = (const float*)d_in[5];
    const float* bv = (const float*)d_in[6];
    const float* wo = (const float*)d_in[7];
    const float* bo = (const float*)d_in[8];
    float* out = (float*)d_out;

    __half* x16;
    cudaGetSymbolAddress((void**)&x16, g_x16);

    const int GEMM_SMEM = 4 * G_STG;   // 65536
    cudaFuncSetAttribute(gemm_mma<0>,
                         cudaFuncAttributeMaxDynamicSharedMemorySize, GEMM_SMEM);
    cudaFuncSetAttribute(gemm_mma<1>,
                         cudaFuncAttributeMaxDynamicSharedMemorySize, GEMM_SMEM);
    cudaFuncSetAttribute(attn_mma,
                         cudaFuncAttributeMaxDynamicSharedMemorySize, ATTN_SMEM_TOT);

    split5_kernel<<<dim3(512, 1, 5), 256>>>((const float4*)wq, (const float4*)wk,
                                            (const float4*)wv, (const float4*)wo,
                                            (const float4*)x);

    gemm_mma<0><<<dim3(DM / 128, SQ / 128, 3), 256, GEMM_SMEM>>>(
        x16, 0, bq, bk, bv, nullptr);

    attn_mma<<<dim3(SQ / 128, NH), 256, ATTN_SMEM_TOT>>>();

    gemm_mma<1><<<dim3(DM / 128, SQ / 128, 1), 256, GEMM_SMEM>>>(
        x16, 3, bo, bo, bo, out);
}